// round 12
// baseline (speedup 1.0000x reference)
#include <cuda_runtime.h>

// Problem constants (fixed by reference)
#define BB   2
#define NN   4096
#define DD   128
#define HH   4
#define HID  32
#define EN   16

#define NSPLIT    4    // j-splits for heads attention   (grid = 32*4*8  = 1024 blocks)
#define NSPLIT_L  16   // j-splits for last attention    (grid = 32*16*2 = 1024 blocks)
#define TJ        64   // j tile staged in SMEM
#define WPR       (NN/32)   // 128 mask words per row

// leakyrelu(s)*log2e = C1*s + C2*|s|   (max(s,0.2s) = 0.6s + 0.4|s|)
#define C1f 0.86561702453870f   // 0.6*log2(e)
#define C2f 0.57707801635913f   // 0.4*log2(e)

// ---------------- scratch (device globals; no allocation allowed) ----------------
__device__ __align__(16) unsigned g_bits[(size_t)BB*NN*WPR];          // 4MB adj bitmask
__device__ __align__(16) float g_wh  [BB*HH*NN*HID];
__device__ __align__(16) float g_wh1 [BB*HH*NN];
__device__ __align__(16) float g_wh2 [BB*HH*NN];
__device__ __align__(16) float g_xcat[(size_t)BB*NN*HH*HID];
__device__ __align__(16) float g_whl [BB*NN*EN];
__device__ __align__(16) float g_wh1l[BB*NN];
__device__ __align__(16) float g_wh2l[BB*NN];
__device__ __align__(16) float g_pacc[(size_t)BB*HH*NSPLIT*NN*HID];
__device__ __align__(16) float g_pZ  [BB*HH*NSPLIT*NN];
__device__ __align__(16) float g_paccl[(size_t)BB*NSPLIT_L*NN*EN];
__device__ __align__(16) float g_pZl [BB*NSPLIT_L*NN];

__device__ __forceinline__ float eluf(float x) { return x > 0.f ? x : expm1f(x); }

__device__ __forceinline__ float ex2f(float x) {
    float r; asm("ex2.approx.ftz.f32 %0,%1;" : "=f"(r) : "f"(x)); return r;
}
__device__ __forceinline__ unsigned long long pack2(float p) {
    unsigned long long r; unsigned u = __float_as_uint(p);
    asm("mov.b64 %0,{%1,%1};" : "=l"(r) : "r"(u));
    return r;
}
__device__ __forceinline__ void fma2(unsigned long long& d, unsigned long long a, unsigned long long b) {
    asm("fma.rn.f32x2 %0,%1,%2,%0;" : "+l"(d) : "l"(a), "l"(b));
}

// ---------------- K0: pack adj into bitmask (read adj ONCE from DRAM) ----------------
// warp per row; coalesced float loads + ballot
__global__ void k0_pack(const float* __restrict__ adj) {
    int warp = (blockIdx.x * blockDim.x + threadIdx.x) >> 5;   // over BB*NN rows
    int lane = threadIdx.x & 31;
    const float* row = adj + (size_t)warp * NN;
    unsigned* dst = g_bits + (size_t)warp * WPR;
#pragma unroll 4
    for (int w = 0; w < WPR; w++) {
        float v = row[w * 32 + lane];
        unsigned b = __ballot_sync(0xffffffffu, v != 0.f);
        if (lane == 0) dst[w] = b;
    }
}

// ---------------- K1: wh = fea @ W_h ; wh1 = wh·a[:32] ; wh2 = wh·a[32:] ----------------
__global__ void k1_wh(const float* __restrict__ fea,
                      const float* __restrict__ Wh,
                      const float* __restrict__ ah) {
    int warp = (blockIdx.x * blockDim.x + threadIdx.x) >> 5;
    int lane = threadIdx.x & 31;
    int i  = warp & (NN - 1);
    int bh = warp >> 12;
    int b = bh >> 2, h = bh & 3;

    const float* xrow = fea + ((size_t)b * NN + i) * DD;
    const float* Wp   = Wh + (size_t)h * DD * HID + lane;

    float a0 = 0.f, a1 = 0.f, a2 = 0.f, a3 = 0.f;
#pragma unroll
    for (int k = 0; k < DD; k += 4) {
        float4 xv = *reinterpret_cast<const float4*>(xrow + k);
        a0 += xv.x * Wp[(k + 0) * HID];
        a1 += xv.y * Wp[(k + 1) * HID];
        a2 += xv.z * Wp[(k + 2) * HID];
        a3 += xv.w * Wp[(k + 3) * HID];
    }
    float acc = (a0 + a1) + (a2 + a3);
    g_wh[((size_t)bh * NN + i) * HID + lane] = acc;

    float v1 = acc * ah[h * 2 * HID + lane];
    float v2 = acc * ah[h * 2 * HID + HID + lane];
#pragma unroll
    for (int off = 16; off; off >>= 1) {
        v1 += __shfl_xor_sync(0xffffffffu, v1, off);
        v2 += __shfl_xor_sync(0xffffffffu, v2, off);
    }
    if (lane == 0) { g_wh1[bh * NN + i] = v1; g_wh2[bh * NN + i] = v2; }
}

// ---------------- K2: fused masked-softmax attention (heads), bitmask edition ----------
// 64 threads, 2 rows/thread (128 rows), one (b,h,split); split = 1024 j's.
__global__ __launch_bounds__(64) void k2_att() {
    int bh = blockIdx.z;
    int i0 = blockIdx.x * 128;
    int sp = blockIdx.y;
    int jbase = sp * (NN / NSPLIT);
    int w0 = sp * (NN / NSPLIT / 32);       // 32 words per split
    int t = threadIdx.x;

    __shared__ unsigned mask_s[128][33];          // split's mask words, padded
    __shared__ __align__(16) float wh_s[TJ * HID];
    __shared__ float2 wh2_s[TJ];

    const float* whp = g_wh + (size_t)bh * NN * HID;
    size_t rowbase = (size_t)((bh >> 2) * NN + i0) * WPR;   // bits indexed by (b,row)

    // stage the whole split's mask words: 128 rows x 32 words
#pragma unroll
    for (int k = 0; k < 16; k++) {
        int q = t + k * 64;             // [0,1024)
        int row = q >> 3, c4 = q & 7;
        uint4 v = *reinterpret_cast<const uint4*>(g_bits + rowbase + (size_t)row * WPR + w0 + c4 * 4);
        mask_s[row][c4 * 4 + 0] = v.x; mask_s[row][c4 * 4 + 1] = v.y;
        mask_s[row][c4 * 4 + 2] = v.z; mask_s[row][c4 * 4 + 3] = v.w;
    }

    int r1 = i0 + t, r2 = i0 + 64 + t;
    float wh1a = g_wh1[bh * NN + r1];
    float wh1b = g_wh1[bh * NN + r2];

    unsigned long long acc1[HID / 2] = {}, acc2[HID / 2] = {};
    float Z1 = 0.f, Z2 = 0.f;

    for (int jt = 0; jt < NN / NSPLIT; jt += TJ) {
        int j0 = jbase + jt;
        __syncthreads();
        {   // stage wh tile: 64 x 32 floats = 512 float4
            const float4* src = reinterpret_cast<const float4*>(whp + (size_t)j0 * HID);
            float4* dst = reinterpret_cast<float4*>(wh_s);
#pragma unroll
            for (int k = 0; k < 8; k++) dst[t + k * 64] = src[t + k * 64];
        }
        {   // duplicated wh2 pairs
            float w2 = g_wh2[bh * NN + j0 + t];
            wh2_s[t] = make_float2(w2, w2);
        }
        __syncthreads();

#pragma unroll
        for (int half = 0; half < 2; half++) {
            unsigned m1 = mask_s[t][(jt >> 5) + half];
            unsigned m2 = mask_s[t + 64][(jt >> 5) + half];
#pragma unroll 8
            for (int jj = 0; jj < 32; jj++) {
                int j = half * 32 + jj;
                float2 w2 = wh2_s[j];
                float s1 = wh1a + w2.x;
                float s2 = wh1b + w2.y;
                float e1 = fmaf(C2f, fabsf(s1), C1f * s1);
                float e2 = fmaf(C2f, fabsf(s2), C1f * s2);
                float p1 = (((m1 >> jj) & 1u) && (s1 != 0.f)) ? ex2f(e1) : 0.f;
                float p2 = (((m2 >> jj) & 1u) && (s2 != 0.f)) ? ex2f(e2) : 0.f;
                Z1 += p1; Z2 += p2;
                unsigned long long pp1 = pack2(p1), pp2 = pack2(p2);
                const ulonglong2* wrow = reinterpret_cast<const ulonglong2*>(&wh_s[j * HID]);
#pragma unroll
                for (int cc = 0; cc < HID / 4; cc++) {
                    ulonglong2 w = wrow[cc];
                    fma2(acc1[cc * 2],     pp1, w.x);
                    fma2(acc1[cc * 2 + 1], pp1, w.y);
                    fma2(acc2[cc * 2],     pp2, w.x);
                    fma2(acc2[cc * 2 + 1], pp2, w.y);
                }
            }
        }
    }

    size_t rb1 = ((size_t)(bh * NSPLIT + sp) * NN + r1);
    size_t rb2 = ((size_t)(bh * NSPLIT + sp) * NN + r2);
#pragma unroll
    for (int cc = 0; cc < HID / 2; cc++) {
        *reinterpret_cast<unsigned long long*>(&g_pacc[rb1 * HID + cc * 2]) = acc1[cc];
        *reinterpret_cast<unsigned long long*>(&g_pacc[rb2 * HID + cc * 2]) = acc2[cc];
    }
    g_pZ[rb1] = Z1;
    g_pZ[rb2] = Z2;
}

// ---------------- K2b: combine splits, divide, ELU, write xcat ----------------
__global__ void k2_comb() {
    int idx = blockIdx.x * 256 + threadIdx.x;
    int c  = idx & (HID - 1);
    int ri = idx >> 5;
    int bh = ri >> 12;
    int i  = ri & (NN - 1);
    float a = 0.f, Z = 0.f;
#pragma unroll
    for (int sp = 0; sp < NSPLIT; sp++) {
        size_t rb = ((size_t)(bh * NSPLIT + sp) << 12) + i;
        a += g_pacc[rb * HID + c];
        Z += g_pZ[rb];
    }
    float v = a / Z;
    int b = bh >> 2, h = bh & 3;
    g_xcat[(((size_t)b << 12) + i) * (HH * HID) + h * HID + c] = eluf(v);
}

// ---------------- K3: wh_last = xcat @ W_last ; wh1l/wh2l ----------------
__global__ void k3_whl(const float* __restrict__ Wl, const float* __restrict__ al) {
    int warp = (blockIdx.x * blockDim.x + threadIdx.x) >> 5;
    int lane = threadIdx.x & 31;
    int b = warp >> 12, i = warp & (NN - 1);
    int c = lane & 15, half = lane >> 4;

    const float* xr = g_xcat + ((size_t)b * NN + i) * (HH * HID) + half * 64;
    float a0 = 0.f, a1 = 0.f;
#pragma unroll
    for (int k = 0; k < 64; k += 8) {
        float4 x0 = *reinterpret_cast<const float4*>(xr + k);
        float4 x1 = *reinterpret_cast<const float4*>(xr + k + 4);
        a0 += x0.x * Wl[(half * 64 + k + 0) * EN + c];
        a1 += x0.y * Wl[(half * 64 + k + 1) * EN + c];
        a0 += x0.z * Wl[(half * 64 + k + 2) * EN + c];
        a1 += x0.w * Wl[(half * 64 + k + 3) * EN + c];
        a0 += x1.x * Wl[(half * 64 + k + 4) * EN + c];
        a1 += x1.y * Wl[(half * 64 + k + 5) * EN + c];
        a0 += x1.z * Wl[(half * 64 + k + 6) * EN + c];
        a1 += x1.w * Wl[(half * 64 + k + 7) * EN + c];
    }
    float acc = a0 + a1;
    acc += __shfl_xor_sync(0xffffffffu, acc, 16);
    if (half == 0) g_whl[((size_t)b * NN + i) * EN + c] = acc;

    float v1 = acc * al[c];
    float v2 = acc * al[EN + c];
#pragma unroll
    for (int off = 8; off; off >>= 1) {
        v1 += __shfl_xor_sync(0xffffffffu, v1, off);
        v2 += __shfl_xor_sync(0xffffffffu, v2, off);
    }
    if (lane == 0) { g_wh1l[b * NN + i] = v1; g_wh2l[b * NN + i] = v2; }
}

// ---------------- K4: last-layer fused attention, bitmask edition ----------------
__global__ __launch_bounds__(64) void k4_att() {
    int b  = blockIdx.z;
    int i0 = blockIdx.x * 128;
    int sp = blockIdx.y;
    int jbase = sp * (NN / NSPLIT_L);              // 256 j's
    int w0 = sp * (NN / NSPLIT_L / 32);            // 8 words per split
    int t = threadIdx.x;

    __shared__ unsigned mask_s[128][9];
    __shared__ __align__(16) float wh_s[TJ * EN];
    __shared__ float2 wh2_s[TJ];

    const float* whp = g_whl + (size_t)b * NN * EN;
    size_t rowbase = (size_t)(b * NN + i0) * WPR;

#pragma unroll
    for (int k = 0; k < 4; k++) {
        int q = t + k * 64;             // [0,256): 128 rows x 2 uint4
        int row = q >> 1, c4 = q & 1;
        uint4 v = *reinterpret_cast<const uint4*>(g_bits + rowbase + (size_t)row * WPR + w0 + c4 * 4);
        mask_s[row][c4 * 4 + 0] = v.x; mask_s[row][c4 * 4 + 1] = v.y;
        mask_s[row][c4 * 4 + 2] = v.z; mask_s[row][c4 * 4 + 3] = v.w;
    }

    int r1 = i0 + t, r2 = i0 + 64 + t;
    float wh1a = g_wh1l[b * NN + r1];
    float wh1b = g_wh1l[b * NN + r2];

    unsigned long long acc1[EN / 2] = {}, acc2[EN / 2] = {};
    float Z1 = 0.f, Z2 = 0.f;

    for (int jt = 0; jt < NN / NSPLIT_L; jt += TJ) {   // 4 tiles
        int j0 = jbase + jt;
        __syncthreads();
        {   // stage wh tile: 64 x 16 floats = 256 float4
            const float4* src = reinterpret_cast<const float4*>(whp + (size_t)j0 * EN);
            float4* dst = reinterpret_cast<float4*>(wh_s);
#pragma unroll
            for (int k = 0; k < 4; k++) dst[t + k * 64] = src[t + k * 64];
        }
        {
            float w2 = g_wh2l[b * NN + j0 + t];
            wh2_s[t] = make_float2(w2, w2);
        }
        __syncthreads();

#pragma unroll
        for (int half = 0; half < 2; half++) {
            unsigned m1 = mask_s[t][(jt >> 5) + half];
            unsigned m2 = mask_s[t + 64][(jt >> 5) + half];
#pragma unroll 8
            for (int jj = 0; jj < 32; jj++) {
                int j = half * 32 + jj;
                float2 w2 = wh2_s[j];
                float s1 = wh1a + w2.x;
                float s2 = wh1b + w2.y;
                float e1 = fmaf(C2f, fabsf(s1), C1f * s1);
                float e2 = fmaf(C2f, fabsf(s2), C1f * s2);
                float p1 = (((m1 >> jj) & 1u) && (s1 != 0.f)) ? ex2f(e1) : 0.f;
                float p2 = (((m2 >> jj) & 1u) && (s2 != 0.f)) ? ex2f(e2) : 0.f;
                Z1 += p1; Z2 += p2;
                unsigned long long pp1 = pack2(p1), pp2 = pack2(p2);
                const ulonglong2* wrow = reinterpret_cast<const ulonglong2*>(&wh_s[j * EN]);
#pragma unroll
                for (int cc = 0; cc < EN / 4; cc++) {
                    ulonglong2 w = wrow[cc];
                    fma2(acc1[cc * 2],     pp1, w.x);
                    fma2(acc1[cc * 2 + 1], pp1, w.y);
                    fma2(acc2[cc * 2],     pp2, w.x);
                    fma2(acc2[cc * 2 + 1], pp2, w.y);
                }
            }
        }
    }

    size_t rb1 = ((size_t)(b * NSPLIT_L + sp) * NN + r1);
    size_t rb2 = ((size_t)(b * NSPLIT_L + sp) * NN + r2);
#pragma unroll
    for (int cc = 0; cc < EN / 2; cc++) {
        *reinterpret_cast<unsigned long long*>(&g_paccl[rb1 * EN + cc * 2]) = acc1[cc];
        *reinterpret_cast<unsigned long long*>(&g_paccl[rb2 * EN + cc * 2]) = acc2[cc];
    }
    g_pZl[rb1] = Z1;
    g_pZl[rb2] = Z2;
}

// ---------------- K4b: combine, divide, outer ELU, write output ----------------
__global__ void k4_comb(float* __restrict__ out) {
    int idx = blockIdx.x * 256 + threadIdx.x;
    int c  = idx & (EN - 1);
    int ri = idx >> 4;
    int b  = ri >> 12;
    int i  = ri & (NN - 1);
    float a = 0.f, Z = 0.f;
#pragma unroll
    for (int sp = 0; sp < NSPLIT_L; sp++) {
        size_t rb = ((size_t)(b * NSPLIT_L + sp) << 12) + i;
        a += g_paccl[rb * EN + c];
        Z += g_pZl[rb];
    }
    out[((size_t)b * NN + i) * EN + c] = eluf(a / Z);
}

// ---------------- launch ----------------
extern "C" void kernel_launch(void* const* d_in, const int* in_sizes, int n_in,
                              void* d_out, int out_size) {
    const float* fea = (const float*)d_in[0];   // [B,N,D]
    const float* adj = (const float*)d_in[1];   // [B,N,N]
    const float* Wh  = (const float*)d_in[2];   // [H,D,HID]
    const float* ah  = (const float*)d_in[3];   // [H,2*HID,1]
    const float* Wl  = (const float*)d_in[4];   // [H*HID,EN]
    const float* al  = (const float*)d_in[5];   // [2*EN,1]
    float* out = (float*)d_out;                 // [B,N,EN]

    (void)in_sizes; (void)n_in; (void)out_size;

    k0_pack<<<(BB * NN) / 8, 256>>>(adj);
    k1_wh  <<<(BB * HH * NN) / 8, 256>>>(fea, Wh, ah);
    k2_att <<<dim3(NN / 128, NSPLIT, BB * HH), 64>>>();
    k2_comb<<<(BB * HH * NN * HID) / 256, 256>>>();
    k3_whl <<<(BB * NN) / 8, 256>>>(Wl, al);
    k4_att <<<dim3(NN / 128, NSPLIT_L, BB), 64>>>();
    k4_comb<<<(BB * NN * EN) / 256, 256>>>(out);
}

// round 14
// speedup vs baseline: 1.1744x; 1.1744x over previous
#include <cuda_runtime.h>
#include <cstdint>

// Problem constants (fixed by reference)
#define BB   2
#define NN   4096
#define DD   128
#define HH   4
#define HID  32
#define EN   16

#define WPR  (NN/32)       // 128 mask words per row
#define CH   64            // j-chunk staged per iteration
#define KS4  4             // K-splits for last-layer attention

// leakyrelu(s)*log2e = C1*s + C2*|s|
#define C1f 0.86561702453870f
#define C2f 0.57707801635913f

// ---------------- scratch (device globals) ----------------
__device__ __align__(16) unsigned g_bits[(size_t)BB*NN*WPR];
__device__ __align__(16) float g_wh  [BB*HH*NN*HID];
__device__ __align__(16) float g_wh1 [BB*HH*NN];
__device__ __align__(16) float g_wh2 [BB*HH*NN];
__device__ __align__(16) float g_xcat[(size_t)BB*NN*HH*HID];
__device__ __align__(16) float g_whl [BB*NN*EN];
__device__ __align__(16) float g_wh1l[BB*NN];
__device__ __align__(16) float g_wh2l[BB*NN];
__device__ __align__(16) float g_paccl[(size_t)BB*KS4*NN*EN];
__device__ __align__(16) float g_pZl [BB*KS4*NN];

// ---------------- helpers ----------------
__device__ __forceinline__ float eluf(float x) { return x > 0.f ? x : expm1f(x); }
__device__ __forceinline__ float ex2f(float x) {
    float r; asm("ex2.approx.ftz.f32 %0,%1;" : "=f"(r) : "f"(x)); return r;
}
__device__ __forceinline__ uint32_t tf32r(float f) {   // round-to-nearest tf32 (portable PTX, sm_80+)
    uint32_t r; asm("cvt.rna.tf32.f32 %0,%1;" : "=r"(r) : "f"(f)); return r;
}
// portable warp MMA: D(16x8) += A(16x8,tf32) * B(8x8,tf32)
__device__ __forceinline__ void mma8(float* c, uint32_t a0, uint32_t a1, uint32_t a2, uint32_t a3,
                                     uint32_t b0, uint32_t b1) {
    asm volatile(
        "mma.sync.aligned.m16n8k8.row.col.f32.tf32.tf32.f32 "
        "{%0,%1,%2,%3},{%4,%5,%6,%7},{%8,%9},{%0,%1,%2,%3};"
        : "+f"(c[0]), "+f"(c[1]), "+f"(c[2]), "+f"(c[3])
        : "r"(a0), "r"(a1), "r"(a2), "r"(a3), "r"(b0), "r"(b1));
}

// ---------------- K0: pack adj into bitmask (read adj once) ----------------
__global__ void k0_pack(const float* __restrict__ adj) {
    int warp = (blockIdx.x * blockDim.x + threadIdx.x) >> 5;
    int lane = threadIdx.x & 31;
    const float* row = adj + (size_t)warp * NN;
    unsigned* dst = g_bits + (size_t)warp * WPR;
#pragma unroll 4
    for (int w = 0; w < WPR; w++) {
        float v = row[w * 32 + lane];
        unsigned b = __ballot_sync(0xffffffffu, v != 0.f);
        if (lane == 0) dst[w] = b;
    }
}

// ---------------- K1: wh = fea @ W_h ; wh1/wh2 ----------------
__global__ void k1_wh(const float* __restrict__ fea,
                      const float* __restrict__ Wh,
                      const float* __restrict__ ah) {
    int warp = (blockIdx.x * blockDim.x + threadIdx.x) >> 5;
    int lane = threadIdx.x & 31;
    int i  = warp & (NN - 1);
    int bh = warp >> 12;
    int b = bh >> 2, h = bh & 3;

    const float* xrow = fea + ((size_t)b * NN + i) * DD;
    const float* Wp   = Wh + (size_t)h * DD * HID + lane;

    float a0 = 0.f, a1 = 0.f, a2 = 0.f, a3 = 0.f;
#pragma unroll
    for (int k = 0; k < DD; k += 4) {
        float4 xv = *reinterpret_cast<const float4*>(xrow + k);
        a0 += xv.x * Wp[(k + 0) * HID];
        a1 += xv.y * Wp[(k + 1) * HID];
        a2 += xv.z * Wp[(k + 2) * HID];
        a3 += xv.w * Wp[(k + 3) * HID];
    }
    float acc = (a0 + a1) + (a2 + a3);
    g_wh[((size_t)bh * NN + i) * HID + lane] = acc;

    float v1 = acc * ah[h * 2 * HID + lane];
    float v2 = acc * ah[h * 2 * HID + HID + lane];
#pragma unroll
    for (int off = 16; off; off >>= 1) {
        v1 += __shfl_xor_sync(0xffffffffu, v1, off);
        v2 += __shfl_xor_sync(0xffffffffu, v2, off);
    }
    if (lane == 0) { g_wh1[bh * NN + i] = v1; g_wh2[bh * NN + i] = v2; }
}

// ---------------- K2: heads attention via warp mma (1xTF32) ----------------
// 128 threads = 4 warps x 16 rows = 64 rows/block; j streamed full 4096 in CH chunks.
__global__ __launch_bounds__(128) void k2t() {
    __shared__ uint32_t bfrag[(CH / 8) * 4 * 64];   // [kchunk(8)][ntile(4)][lane(32)][reg(2)]
    __shared__ float wh2s[CH];

    int t = threadIdx.x, lane = t & 31, w = t >> 5;
    int bh = blockIdx.y, b = bh >> 2, h = bh & 3;
    int i0 = blockIdx.x * 64;
    int row_lo = i0 + w * 16 + (lane >> 2);          // global row for a0/a2
    int qid = lane & 3;

    float wh1_lo = g_wh1[bh * NN + row_lo];
    float wh1_hi = g_wh1[bh * NN + row_lo + 8];
    const unsigned* bits_lo = g_bits + (size_t)(b * NN + row_lo) * WPR;
    const unsigned* bits_hi = bits_lo + 8 * WPR;
    const float* whp  = g_wh + (size_t)bh * NN * HID;
    const float* wh2g = g_wh2 + bh * NN;

    float C[4][4] = {};
    float zlo = 0.f, zhi = 0.f;

    for (int j0 = 0; j0 < NN; j0 += CH) {
        __syncthreads();
        // stage W tile (CH x 32) into B-fragment order, tf32
#pragma unroll
        for (int k = 0; k < 4; k++) {
            int f = t + k * 128;                     // 512 float4 total
            int jj = f >> 3, c4 = (f & 7) * 4;
            float4 v = *reinterpret_cast<const float4*>(whp + (size_t)(j0 + jj) * HID + c4);
            int kchunk = jj >> 3, kk = jj & 7, reg = kk >> 2, lsub = kk & 3;
            float vv[4] = { v.x, v.y, v.z, v.w };
#pragma unroll
            for (int u = 0; u < 4; u++) {
                int c = c4 + u, ntile = c >> 3, nn = c & 7;
                bfrag[((kchunk * 4 + ntile) * 32 + nn * 4 + lsub) * 2 + reg] = tf32r(vv[u]);
            }
        }
        if (t < CH) wh2s[t] = wh2g[j0 + t];
        int jw = j0 >> 5;
        unsigned mlo0 = bits_lo[jw], mlo1 = bits_lo[jw + 1];
        unsigned mhi0 = bits_hi[jw], mhi1 = bits_hi[jw + 1];
        __syncthreads();

#pragma unroll
        for (int kc = 0; kc < CH / 8; kc++) {
            unsigned wlo = (kc < 4) ? mlo0 : mlo1;
            unsigned whi = (kc < 4) ? mhi0 : mhi1;
            int shw = (kc * 8 + qid) & 31;
            unsigned blo = wlo >> shw, bhi = whi >> shw;
            float w2a = wh2s[kc * 8 + qid];
            float w2b = wh2s[kc * 8 + qid + 4];

            float s0 = wh1_lo + w2a, s1 = wh1_hi + w2a;
            float s2 = wh1_lo + w2b, s3 = wh1_hi + w2b;
            float e0 = fmaf(C2f, fabsf(s0), C1f * s0);
            float e1 = fmaf(C2f, fabsf(s1), C1f * s1);
            float e2 = fmaf(C2f, fabsf(s2), C1f * s2);
            float e3 = fmaf(C2f, fabsf(s3), C1f * s3);
            float p0 = ((blo & 1u)  && s0 != 0.f) ? ex2f(e0) : 0.f;
            float p1 = ((bhi & 1u)  && s1 != 0.f) ? ex2f(e1) : 0.f;
            float p2 = ((blo & 16u) && s2 != 0.f) ? ex2f(e2) : 0.f;
            float p3 = ((bhi & 16u) && s3 != 0.f) ? ex2f(e3) : 0.f;
            zlo += p0 + p2; zhi += p1 + p3;
            uint32_t a0 = tf32r(p0), a1 = tf32r(p1), a2 = tf32r(p2), a3 = tf32r(p3);

            const uint2* bq = reinterpret_cast<const uint2*>(bfrag) + (kc * 4) * 32;
#pragma unroll
            for (int nt = 0; nt < 4; nt++) {
                uint2 bv = bq[nt * 32 + lane];
                mma8(C[nt], a0, a1, a2, a3, bv.x, bv.y);
            }
        }
    }

    // reduce Z across the 4 lanes of each row quad
    zlo += __shfl_xor_sync(0xffffffffu, zlo, 1);
    zlo += __shfl_xor_sync(0xffffffffu, zlo, 2);
    zhi += __shfl_xor_sync(0xffffffffu, zhi, 1);
    zhi += __shfl_xor_sync(0xffffffffu, zhi, 2);
    float ilo = 1.f / zlo, ihi = 1.f / zhi;

    float* dlo = g_xcat + (size_t)(b * NN + row_lo) * (HH * HID) + h * HID + qid * 2;
    float* dhi = dlo + (size_t)8 * (HH * HID);
#pragma unroll
    for (int nt = 0; nt < 4; nt++) {
        float2 o;
        o.x = eluf(C[nt][0] * ilo); o.y = eluf(C[nt][1] * ilo);
        *reinterpret_cast<float2*>(dlo + nt * 8) = o;
        o.x = eluf(C[nt][2] * ihi); o.y = eluf(C[nt][3] * ihi);
        *reinterpret_cast<float2*>(dhi + nt * 8) = o;
    }
}

// ---------------- K3: wh_last = xcat @ W_last ; wh1l/wh2l ----------------
__global__ void k3_whl(const float* __restrict__ Wl, const float* __restrict__ al) {
    int warp = (blockIdx.x * blockDim.x + threadIdx.x) >> 5;
    int lane = threadIdx.x & 31;
    int b = warp >> 12, i = warp & (NN - 1);
    int c = lane & 15, half = lane >> 4;

    const float* xr = g_xcat + ((size_t)b * NN + i) * (HH * HID) + half * 64;
    float a0 = 0.f, a1 = 0.f;
#pragma unroll
    for (int k = 0; k < 64; k += 8) {
        float4 x0 = *reinterpret_cast<const float4*>(xr + k);
        float4 x1 = *reinterpret_cast<const float4*>(xr + k + 4);
        a0 += x0.x * Wl[(half * 64 + k + 0) * EN + c];
        a1 += x0.y * Wl[(half * 64 + k + 1) * EN + c];
        a0 += x0.z * Wl[(half * 64 + k + 2) * EN + c];
        a1 += x0.w * Wl[(half * 64 + k + 3) * EN + c];
        a0 += x1.x * Wl[(half * 64 + k + 4) * EN + c];
        a1 += x1.y * Wl[(half * 64 + k + 5) * EN + c];
        a0 += x1.z * Wl[(half * 64 + k + 6) * EN + c];
        a1 += x1.w * Wl[(half * 64 + k + 7) * EN + c];
    }
    float acc = a0 + a1;
    acc += __shfl_xor_sync(0xffffffffu, acc, 16);
    if (half == 0) g_whl[((size_t)b * NN + i) * EN + c] = acc;

    float v1 = acc * al[c];
    float v2 = acc * al[EN + c];
#pragma unroll
    for (int off = 8; off; off >>= 1) {
        v1 += __shfl_xor_sync(0xffffffffu, v1, off);
        v2 += __shfl_xor_sync(0xffffffffu, v2, off);
    }
    if (lane == 0) { g_wh1l[b * NN + i] = v1; g_wh2l[b * NN + i] = v2; }
}

// ---------------- K4: last-layer attention via warp mma (3xTF32), K-split x4 ----------------
__global__ __launch_bounds__(128) void k4t() {
    __shared__ uint32_t bfragH[(CH / 8) * 2 * 64];   // 1024
    __shared__ uint32_t bfragL[(CH / 8) * 2 * 64];
    __shared__ float wh2s[CH];

    int t = threadIdx.x, lane = t & 31, w = t >> 5;
    int b  = blockIdx.z;
    int ks = blockIdx.y;
    int i0 = blockIdx.x * 64;
    int jbase = ks * (NN / KS4);
    int row_lo = i0 + w * 16 + (lane >> 2);
    int qid = lane & 3;

    float wh1_lo = g_wh1l[b * NN + row_lo];
    float wh1_hi = g_wh1l[b * NN + row_lo + 8];
    const unsigned* bits_lo = g_bits + (size_t)(b * NN + row_lo) * WPR;
    const unsigned* bits_hi = bits_lo + 8 * WPR;
    const float* whp  = g_whl + (size_t)b * NN * EN;
    const float* wh2g = g_wh2l + b * NN;

    float C[2][4] = {};
    float zlo = 0.f, zhi = 0.f;

    for (int jt = 0; jt < NN / KS4; jt += CH) {
        int j0 = jbase + jt;
        __syncthreads();
        // stage W tile (CH x 16) hi/lo in B-fragment order
#pragma unroll
        for (int k = 0; k < 2; k++) {
            int f = t + k * 128;                 // 256 float4 total
            int jj = f >> 2, c4 = (f & 3) * 4;
            float4 v = *reinterpret_cast<const float4*>(whp + (size_t)(j0 + jj) * EN + c4);
            int kchunk = jj >> 3, kk = jj & 7, reg = kk >> 2, lsub = kk & 3;
            float vv[4] = { v.x, v.y, v.z, v.w };
#pragma unroll
            for (int u = 0; u < 4; u++) {
                int c = c4 + u, ntile = c >> 3, nn = c & 7;
                int idx = ((kchunk * 2 + ntile) * 32 + nn * 4 + lsub) * 2 + reg;
                uint32_t hi = tf32r(vv[u]);
                bfragH[idx] = hi;
                bfragL[idx] = tf32r(vv[u] - __uint_as_float(hi));
            }
        }
        if (t < CH) wh2s[t] = wh2g[j0 + t];
        int jw = j0 >> 5;
        unsigned mlo0 = bits_lo[jw], mlo1 = bits_lo[jw + 1];
        unsigned mhi0 = bits_hi[jw], mhi1 = bits_hi[jw + 1];
        __syncthreads();

#pragma unroll
        for (int kc = 0; kc < CH / 8; kc++) {
            unsigned wlo = (kc < 4) ? mlo0 : mlo1;
            unsigned whi = (kc < 4) ? mhi0 : mhi1;
            int shw = (kc * 8 + qid) & 31;
            unsigned blo = wlo >> shw, bhi = whi >> shw;
            float w2a = wh2s[kc * 8 + qid];
            float w2b = wh2s[kc * 8 + qid + 4];

            float s0 = wh1_lo + w2a, s1 = wh1_hi + w2a;
            float s2 = wh1_lo + w2b, s3 = wh1_hi + w2b;
            float e0 = fmaf(C2f, fabsf(s0), C1f * s0);
            float e1 = fmaf(C2f, fabsf(s1), C1f * s1);
            float e2 = fmaf(C2f, fabsf(s2), C1f * s2);
            float e3 = fmaf(C2f, fabsf(s3), C1f * s3);
            float p0 = ((blo & 1u)  && s0 != 0.f) ? ex2f(e0) : 0.f;
            float p1 = ((bhi & 1u)  && s1 != 0.f) ? ex2f(e1) : 0.f;
            float p2 = ((blo & 16u) && s2 != 0.f) ? ex2f(e2) : 0.f;
            float p3 = ((bhi & 16u) && s3 != 0.f) ? ex2f(e3) : 0.f;
            zlo += p0 + p2; zhi += p1 + p3;

            uint32_t aH0 = tf32r(p0), aH1 = tf32r(p1), aH2 = tf32r(p2), aH3 = tf32r(p3);
            uint32_t aL0 = tf32r(p0 - __uint_as_float(aH0));
            uint32_t aL1 = tf32r(p1 - __uint_as_float(aH1));
            uint32_t aL2 = tf32r(p2 - __uint_as_float(aH2));
            uint32_t aL3 = tf32r(p3 - __uint_as_float(aH3));

            const uint2* bqH = reinterpret_cast<const uint2*>(bfragH) + (kc * 2) * 32;
            const uint2* bqL = reinterpret_cast<const uint2*>(bfragL) + (kc * 2) * 32;
#pragma unroll
            for (int nt = 0; nt < 2; nt++) {
                uint2 bh2 = bqH[nt * 32 + lane];
                uint2 bl2 = bqL[nt * 32 + lane];
                mma8(C[nt], aH0, aH1, aH2, aH3, bh2.x, bh2.y);   // hi*hi
                mma8(C[nt], aH0, aH1, aH2, aH3, bl2.x, bl2.y);   // hi*lo
                mma8(C[nt], aL0, aL1, aL2, aL3, bh2.x, bh2.y);   // lo*hi
            }
        }
    }

    zlo += __shfl_xor_sync(0xffffffffu, zlo, 1);
    zlo += __shfl_xor_sync(0xffffffffu, zlo, 2);
    zhi += __shfl_xor_sync(0xffffffffu, zhi, 1);
    zhi += __shfl_xor_sync(0xffffffffu, zhi, 2);

    size_t rb_lo = (size_t)((b * KS4 + ks) * NN + row_lo);
    size_t rb_hi = rb_lo + 8;
    float* dlo = g_paccl + rb_lo * EN + qid * 2;
    float* dhi = g_paccl + rb_hi * EN + qid * 2;
#pragma unroll
    for (int nt = 0; nt < 2; nt++) {
        *reinterpret_cast<float2*>(dlo + nt * 8) = make_float2(C[nt][0], C[nt][1]);
        *reinterpret_cast<float2*>(dhi + nt * 8) = make_float2(C[nt][2], C[nt][3]);
    }
    if (qid == 0) { g_pZl[rb_lo] = zlo; g_pZl[rb_hi] = zhi; }
}

// ---------------- K4b: combine K-splits, divide, ELU, write output ----------------
__global__ void k4_comb(float* __restrict__ out) {
    int idx = blockIdx.x * 256 + threadIdx.x;
    int c  = idx & (EN - 1);
    int ri = idx >> 4;
    int b  = ri >> 12;
    int i  = ri & (NN - 1);
    float a = 0.f, Z = 0.f;
#pragma unroll
    for (int sp = 0; sp < KS4; sp++) {
        size_t rb = ((size_t)(b * KS4 + sp) << 12) + i;
        a += g_paccl[rb * EN + c];
        Z += g_pZl[rb];
    }
    out[((size_t)b * NN + i) * EN + c] = eluf(a / Z);
}

// ---------------- launch ----------------
extern "C" void kernel_launch(void* const* d_in, const int* in_sizes, int n_in,
                              void* d_out, int out_size) {
    const float* fea = (const float*)d_in[0];   // [B,N,D]
    const float* adj = (const float*)d_in[1];   // [B,N,N]
    const float* Wh  = (const float*)d_in[2];   // [H,D,HID]
    const float* ah  = (const float*)d_in[3];   // [H,2*HID,1]
    const float* Wl  = (const float*)d_in[4];   // [H*HID,EN]
    const float* al  = (const float*)d_in[5];   // [2*EN,1]
    float* out = (float*)d_out;                 // [B,N,EN]

    (void)in_sizes; (void)n_in; (void)out_size;

    k0_pack<<<(BB * NN) / 8, 256>>>(adj);
    k1_wh  <<<(BB * HH * NN) / 8, 256>>>(fea, Wh, ah);
    k2t    <<<dim3(NN / 64, BB * HH), 128>>>();
    k3_whl <<<(BB * NN) / 8, 256>>>(Wl, al);
    k4t    <<<dim3(NN / 64, KS4, BB), 128>>>();
    k4_comb<<<(BB * NN * EN) / 256, 256>>>(out);
}

// round 15
// speedup vs baseline: 1.6209x; 1.3801x over previous
#include <cuda_runtime.h>
#include <cstdint>

// Problem constants (fixed by reference)
#define BB   2
#define NN   4096
#define DD   128
#define HH   4
#define HID  32
#define EN   16

#define WPR  (NN/32)       // 128 mask words per row
#define CH   64            // j-chunk staged per iteration
#define NSP2 2             // j-splits, heads attention
#define KS8  8             // j-splits, last attention
#define PAD2 40            // row pad (words) heads tile  -> conflict-free B LDS
#define PAD4 24            // row pad (words) last tile

// leakyrelu(s)*log2e = C1*s + C2*|s|
#define C1f 0.86561702453870f
#define C2f 0.57707801635913f

// ---------------- scratch (device globals) ----------------
__device__ __align__(16) unsigned g_bits[(size_t)BB*NN*WPR];
__device__ __align__(16) float g_wh  [BB*HH*NN*HID];
__device__ __align__(16) float g_wh1 [BB*HH*NN];
__device__ __align__(16) float g_wh2 [BB*HH*NN];
__device__ __align__(16) float g_xcat[(size_t)BB*NN*HH*HID];
__device__ __align__(16) float g_whl [BB*NN*EN];
__device__ __align__(16) float g_wh1l[BB*NN];
__device__ __align__(16) float g_wh2l[BB*NN];
__device__ __align__(16) float g_pacc[(size_t)BB*HH*NSP2*NN*HID];   // 32MB
__device__ __align__(16) float g_pZ  [BB*HH*NSP2*NN];
__device__ __align__(16) float g_paccl[(size_t)BB*KS8*NN*EN];       // 4MB
__device__ __align__(16) float g_pZl [BB*KS8*NN];

// ---------------- helpers ----------------
__device__ __forceinline__ float eluf(float x) { return x > 0.f ? x : expm1f(x); }
__device__ __forceinline__ float ex2f(float x) {
    float r; asm("ex2.approx.ftz.f32 %0,%1;" : "=f"(r) : "f"(x)); return r;
}
__device__ __forceinline__ uint32_t tf32r(float f) {   // round-to-nearest tf32
    uint32_t r; asm("cvt.rna.tf32.f32 %0,%1;" : "=r"(r) : "f"(f)); return r;
}
__device__ __forceinline__ void mma8(float* c, uint32_t a0, uint32_t a1, uint32_t a2, uint32_t a3,
                                     uint32_t b0, uint32_t b1) {
    asm volatile(
        "mma.sync.aligned.m16n8k8.row.col.f32.tf32.tf32.f32 "
        "{%0,%1,%2,%3},{%4,%5,%6,%7},{%8,%9},{%0,%1,%2,%3};"
        : "+f"(c[0]), "+f"(c[1]), "+f"(c[2]), "+f"(c[3])
        : "r"(a0), "r"(a1), "r"(a2), "r"(a3), "r"(b0), "r"(b1));
}

// ---------------- K0: pack adj into bitmask (read adj once) ----------------
__global__ void k0_pack(const float* __restrict__ adj) {
    int warp = (blockIdx.x * blockDim.x + threadIdx.x) >> 5;
    int lane = threadIdx.x & 31;
    const float* row = adj + (size_t)warp * NN;
    unsigned* dst = g_bits + (size_t)warp * WPR;
#pragma unroll 4
    for (int w = 0; w < WPR; w++) {
        float v = row[w * 32 + lane];
        unsigned b = __ballot_sync(0xffffffffu, v != 0.f);
        if (lane == 0) dst[w] = b;
    }
}

// ---------------- K1: wh = fea @ W_h ; wh1/wh2 ----------------
__global__ void k1_wh(const float* __restrict__ fea,
                      const float* __restrict__ Wh,
                      const float* __restrict__ ah) {
    int warp = (blockIdx.x * blockDim.x + threadIdx.x) >> 5;
    int lane = threadIdx.x & 31;
    int i  = warp & (NN - 1);
    int bh = warp >> 12;
    int b = bh >> 2, h = bh & 3;

    const float* xrow = fea + ((size_t)b * NN + i) * DD;
    const float* Wp   = Wh + (size_t)h * DD * HID + lane;

    float a0 = 0.f, a1 = 0.f, a2 = 0.f, a3 = 0.f;
#pragma unroll
    for (int k = 0; k < DD; k += 4) {
        float4 xv = *reinterpret_cast<const float4*>(xrow + k);
        a0 += xv.x * Wp[(k + 0) * HID];
        a1 += xv.y * Wp[(k + 1) * HID];
        a2 += xv.z * Wp[(k + 2) * HID];
        a3 += xv.w * Wp[(k + 3) * HID];
    }
    float acc = (a0 + a1) + (a2 + a3);
    g_wh[((size_t)bh * NN + i) * HID + lane] = acc;

    float v1 = acc * ah[h * 2 * HID + lane];
    float v2 = acc * ah[h * 2 * HID + HID + lane];
#pragma unroll
    for (int off = 16; off; off >>= 1) {
        v1 += __shfl_xor_sync(0xffffffffu, v1, off);
        v2 += __shfl_xor_sync(0xffffffffu, v2, off);
    }
    if (lane == 0) { g_wh1[bh * NN + i] = v1; g_wh2[bh * NN + i] = v2; }
}

// ---------------- K2: heads attention, warp mma, j-split x2, prefetch ----------------
// 128 threads = 4 warps x 16 rows = 64 rows/block; 2048 j per block in CH chunks.
__global__ __launch_bounds__(128, 6) void k2t() {
    __shared__ uint32_t whs[CH * PAD2];     // row-major tf32 tile, padded rows
    __shared__ float wh2s[CH];

    int t = threadIdx.x, lane = t & 31, w = t >> 5;
    int bh = blockIdx.z, b = bh >> 2;
    int sp = blockIdx.y;
    int i0 = blockIdx.x * 64;
    int jbase = sp * (NN / NSP2);
    int row_lo = i0 + w * 16 + (lane >> 2);
    int qid = lane & 3, nn = lane >> 2;

    float wh1_lo = g_wh1[bh * NN + row_lo];
    float wh1_hi = g_wh1[bh * NN + row_lo + 8];
    const unsigned* bits_lo = g_bits + (size_t)(b * NN + row_lo) * WPR;
    const unsigned* bits_hi = bits_lo + 8 * WPR;
    const float* whp  = g_wh + (size_t)bh * NN * HID;
    const float* wh2g = g_wh2 + bh * NN;

    float C[4][4] = {};
    float zlo = 0.f, zhi = 0.f;

    // prefetch regs
    float4 rv[4];
    float rw2 = 0.f;
    unsigned nml0, nml1, nmh0, nmh1;

    {   // load chunk 0
        int j0 = jbase;
#pragma unroll
        for (int k = 0; k < 4; k++) {
            int f = t + k * 128, jj = f >> 3, c4 = (f & 7) * 4;
            rv[k] = *reinterpret_cast<const float4*>(whp + (size_t)(j0 + jj) * HID + c4);
        }
        if (t < CH) rw2 = wh2g[j0 + t];
        int jw = j0 >> 5;
        nml0 = bits_lo[jw]; nml1 = bits_lo[jw + 1];
        nmh0 = bits_hi[jw]; nmh1 = bits_hi[jw + 1];
    }

    const int NCH = (NN / NSP2) / CH;        // 32
    for (int c = 0; c < NCH; c++) {
        __syncthreads();
        // store staged tile (cvt to tf32, STS.128, conflict-free phases)
#pragma unroll
        for (int k = 0; k < 4; k++) {
            int f = t + k * 128, jj = f >> 3, c4 = (f & 7) * 4;
            uint4 u;
            u.x = tf32r(rv[k].x); u.y = tf32r(rv[k].y);
            u.z = tf32r(rv[k].z); u.w = tf32r(rv[k].w);
            *reinterpret_cast<uint4*>(&whs[jj * PAD2 + c4]) = u;
        }
        if (t < CH) wh2s[t] = rw2;
        unsigned ml0 = nml0, ml1 = nml1, mh0 = nmh0, mh1 = nmh1;
        __syncthreads();

        if (c + 1 < NCH) {                   // prefetch next chunk (overlaps compute)
            int j0 = jbase + (c + 1) * CH;
#pragma unroll
            for (int k = 0; k < 4; k++) {
                int f = t + k * 128, jj = f >> 3, c4 = (f & 7) * 4;
                rv[k] = *reinterpret_cast<const float4*>(whp + (size_t)(j0 + jj) * HID + c4);
            }
            if (t < CH) rw2 = wh2g[j0 + t];
            int jw = j0 >> 5;
            nml0 = bits_lo[jw]; nml1 = bits_lo[jw + 1];
            nmh0 = bits_hi[jw]; nmh1 = bits_hi[jw + 1];
        }

#pragma unroll
        for (int kc = 0; kc < CH / 8; kc++) {
            unsigned wlo = (kc < 4) ? ml0 : ml1;
            unsigned whi = (kc < 4) ? mh0 : mh1;
            int sh = (kc * 8 + qid) & 31;
            unsigned blo = wlo >> sh, bhi = whi >> sh;
            float w2a = wh2s[kc * 8 + qid];
            float w2b = wh2s[kc * 8 + qid + 4];

            float s0 = wh1_lo + w2a, s1 = wh1_hi + w2a;
            float s2 = wh1_lo + w2b, s3 = wh1_hi + w2b;
            float e0 = fmaf(C2f, fabsf(s0), C1f * s0);
            float e1 = fmaf(C2f, fabsf(s1), C1f * s1);
            float e2 = fmaf(C2f, fabsf(s2), C1f * s2);
            float e3 = fmaf(C2f, fabsf(s3), C1f * s3);
            float p0 = ((blo & 1u)  && s0 != 0.f) ? ex2f(e0) : 0.f;
            float p1 = ((bhi & 1u)  && s1 != 0.f) ? ex2f(e1) : 0.f;
            float p2 = ((blo & 16u) && s2 != 0.f) ? ex2f(e2) : 0.f;
            float p3 = ((bhi & 16u) && s3 != 0.f) ? ex2f(e3) : 0.f;
            zlo += p0 + p2; zhi += p1 + p3;
            uint32_t a0 = tf32r(p0), a1 = tf32r(p1), a2 = tf32r(p2), a3 = tf32r(p3);

            const uint32_t* b0p = &whs[(kc * 8 + qid) * PAD2 + nn];
            const uint32_t* b1p = b0p + 4 * PAD2;
#pragma unroll
            for (int nt = 0; nt < 4; nt++)
                mma8(C[nt], a0, a1, a2, a3, b0p[nt * 8], b1p[nt * 8]);
        }
    }

    zlo += __shfl_xor_sync(0xffffffffu, zlo, 1);
    zlo += __shfl_xor_sync(0xffffffffu, zlo, 2);
    zhi += __shfl_xor_sync(0xffffffffu, zhi, 1);
    zhi += __shfl_xor_sync(0xffffffffu, zhi, 2);

    size_t rb = (size_t)((bh * NSP2 + sp) * NN + row_lo);
    float* dlo = g_pacc + rb * HID + qid * 2;
    float* dhi = g_pacc + (rb + 8) * HID + qid * 2;
#pragma unroll
    for (int nt = 0; nt < 4; nt++) {
        *reinterpret_cast<float2*>(dlo + nt * 8) = make_float2(C[nt][0], C[nt][1]);
        *reinterpret_cast<float2*>(dhi + nt * 8) = make_float2(C[nt][2], C[nt][3]);
    }
    if (qid == 0) { g_pZ[rb] = zlo; g_pZ[rb + 8] = zhi; }
}

// ---------------- K2b: combine splits, divide, ELU, write xcat ----------------
__global__ void k2_comb() {
    int idx = blockIdx.x * 256 + threadIdx.x;       // over BB*HH*NN*HID
    int c  = idx & (HID - 1);
    int ri = idx >> 5;
    int bh = ri >> 12;
    int i  = ri & (NN - 1);
    float a = 0.f, Z = 0.f;
#pragma unroll
    for (int sp = 0; sp < NSP2; sp++) {
        size_t rb = ((size_t)(bh * NSP2 + sp) << 12) + i;
        a += g_pacc[rb * HID + c];
        Z += g_pZ[rb];
    }
    int b = bh >> 2, h = bh & 3;
    g_xcat[(((size_t)b << 12) + i) * (HH * HID) + h * HID + c] = eluf(a / Z);
}

// ---------------- K3: wh_last = xcat @ W_last ; wh1l/wh2l (smem weights) ----------------
__global__ __launch_bounds__(256) void k3_whl(const float* __restrict__ Wl, const float* __restrict__ al) {
    __shared__ float Wls[128 * EN];
    __shared__ float als[2 * EN];
    int t = threadIdx.x;
#pragma unroll
    for (int u = 0; u < 8; u++) Wls[t + u * 256] = Wl[t + u * 256];
    if (t < 2 * EN) als[t] = al[t];
    __syncthreads();

    int warp = (blockIdx.x * 256 + t) >> 5;
    int lane = t & 31;
    int b = warp >> 12, i = warp & (NN - 1);
    int c = lane & 15, half = lane >> 4;

    const float* xr = g_xcat + ((size_t)b * NN + i) * (HH * HID) + half * 64;
    const float* Wp = Wls + half * 64 * EN + c;
    float a0 = 0.f, a1 = 0.f;
#pragma unroll
    for (int k = 0; k < 64; k += 4) {
        float4 xv = *reinterpret_cast<const float4*>(xr + k);
        a0 += xv.x * Wp[(k + 0) * EN];
        a1 += xv.y * Wp[(k + 1) * EN];
        a0 += xv.z * Wp[(k + 2) * EN];
        a1 += xv.w * Wp[(k + 3) * EN];
    }
    float acc = a0 + a1;
    acc += __shfl_xor_sync(0xffffffffu, acc, 16);
    if (half == 0) g_whl[((size_t)b * NN + i) * EN + c] = acc;

    float v1 = acc * als[c];
    float v2 = acc * als[EN + c];
#pragma unroll
    for (int off = 8; off; off >>= 1) {
        v1 += __shfl_xor_sync(0xffffffffu, v1, off);
        v2 += __shfl_xor_sync(0xffffffffu, v2, off);
    }
    if (lane == 0) { g_wh1l[b * NN + i] = v1; g_wh2l[b * NN + i] = v2; }
}

// ---------------- K4: last-layer attention, warp mma 1xTF32, j-split x8, prefetch ------
__global__ __launch_bounds__(128, 6) void k4t() {
    __shared__ uint32_t whs[CH * PAD4];
    __shared__ float wh2s[CH];

    int t = threadIdx.x, lane = t & 31, w = t >> 5;
    int b  = blockIdx.z;
    int ks = blockIdx.y;
    int i0 = blockIdx.x * 64;
    int jbase = ks * (NN / KS8);             // 512 j per block
    int row_lo = i0 + w * 16 + (lane >> 2);
    int qid = lane & 3, nn = lane >> 2;

    float wh1_lo = g_wh1l[b * NN + row_lo];
    float wh1_hi = g_wh1l[b * NN + row_lo + 8];
    const unsigned* bits_lo = g_bits + (size_t)(b * NN + row_lo) * WPR;
    const unsigned* bits_hi = bits_lo + 8 * WPR;
    const float* whp  = g_whl + (size_t)b * NN * EN;
    const float* wh2g = g_wh2l + b * NN;

    float C[2][4] = {};
    float zlo = 0.f, zhi = 0.f;

    float4 rv[2];
    float rw2 = 0.f;
    unsigned nml0, nml1, nmh0, nmh1;

    {
        int j0 = jbase;
#pragma unroll
        for (int k = 0; k < 2; k++) {
            int f = t + k * 128, jj = f >> 2, c4 = (f & 3) * 4;
            rv[k] = *reinterpret_cast<const float4*>(whp + (size_t)(j0 + jj) * EN + c4);
        }
        if (t < CH) rw2 = wh2g[j0 + t];
        int jw = j0 >> 5;
        nml0 = bits_lo[jw]; nml1 = bits_lo[jw + 1];
        nmh0 = bits_hi[jw]; nmh1 = bits_hi[jw + 1];
    }

    const int NCH = (NN / KS8) / CH;         // 8
    for (int c = 0; c < NCH; c++) {
        __syncthreads();
#pragma unroll
        for (int k = 0; k < 2; k++) {
            int f = t + k * 128, jj = f >> 2, c4 = (f & 3) * 4;
            uint4 u;
            u.x = tf32r(rv[k].x); u.y = tf32r(rv[k].y);
            u.z = tf32r(rv[k].z); u.w = tf32r(rv[k].w);
            *reinterpret_cast<uint4*>(&whs[jj * PAD4 + c4]) = u;
        }
        if (t < CH) wh2s[t] = rw2;
        unsigned ml0 = nml0, ml1 = nml1, mh0 = nmh0, mh1 = nmh1;
        __syncthreads();

        if (c + 1 < NCH) {
            int j0 = jbase + (c + 1) * CH;
#pragma unroll
            for (int k = 0; k < 2; k++) {
                int f = t + k * 128, jj = f >> 2, c4 = (f & 3) * 4;
                rv[k] = *reinterpret_cast<const float4*>(whp + (size_t)(j0 + jj) * EN + c4);
            }
            if (t < CH) rw2 = wh2g[j0 + t];
            int jw = j0 >> 5;
            nml0 = bits_lo[jw]; nml1 = bits_lo[jw + 1];
            nmh0 = bits_hi[jw]; nmh1 = bits_hi[jw + 1];
        }

#pragma unroll
        for (int kc = 0; kc < CH / 8; kc++) {
            unsigned wlo = (kc < 4) ? ml0 : ml1;
            unsigned whi = (kc < 4) ? mh0 : mh1;
            int sh = (kc * 8 + qid) & 31;
            unsigned blo = wlo >> sh, bhi = whi >> sh;
            float w2a = wh2s[kc * 8 + qid];
            float w2b = wh2s[kc * 8 + qid + 4];

            float s0 = wh1_lo + w2a, s1 = wh1_hi + w2a;
            float s2 = wh1_lo + w2b, s3 = wh1_hi + w2b;
            float e0 = fmaf(C2f, fabsf(s0), C1f * s0);
            float e1 = fmaf(C2f, fabsf(s1), C1f * s1);
            float e2 = fmaf(C2f, fabsf(s2), C1f * s2);
            float e3 = fmaf(C2f, fabsf(s3), C1f * s3);
            float p0 = ((blo & 1u)  && s0 != 0.f) ? ex2f(e0) : 0.f;
            float p1 = ((bhi & 1u)  && s1 != 0.f) ? ex2f(e1) : 0.f;
            float p2 = ((blo & 16u) && s2 != 0.f) ? ex2f(e2) : 0.f;
            float p3 = ((bhi & 16u) && s3 != 0.f) ? ex2f(e3) : 0.f;
            zlo += p0 + p2; zhi += p1 + p3;
            uint32_t a0 = tf32r(p0), a1 = tf32r(p1), a2 = tf32r(p2), a3 = tf32r(p3);

            const uint32_t* b0p = &whs[(kc * 8 + qid) * PAD4 + nn];
            const uint32_t* b1p = b0p + 4 * PAD4;
#pragma unroll
            for (int nt = 0; nt < 2; nt++)
                mma8(C[nt], a0, a1, a2, a3, b0p[nt * 8], b1p[nt * 8]);
        }
    }

    zlo += __shfl_xor_sync(0xffffffffu, zlo, 1);
    zlo += __shfl_xor_sync(0xffffffffu, zlo, 2);
    zhi += __shfl_xor_sync(0xffffffffu, zhi, 1);
    zhi += __shfl_xor_sync(0xffffffffu, zhi, 2);

    size_t rb = (size_t)((b * KS8 + ks) * NN + row_lo);
    float* dlo = g_paccl + rb * EN + qid * 2;
    float* dhi = g_paccl + (rb + 8) * EN + qid * 2;
#pragma unroll
    for (int nt = 0; nt < 2; nt++) {
        *reinterpret_cast<float2*>(dlo + nt * 8) = make_float2(C[nt][0], C[nt][1]);
        *reinterpret_cast<float2*>(dhi + nt * 8) = make_float2(C[nt][2], C[nt][3]);
    }
    if (qid == 0) { g_pZl[rb] = zlo; g_pZl[rb + 8] = zhi; }
}

// ---------------- K4b: combine splits, divide, ELU, write output ----------------
__global__ void k4_comb(float* __restrict__ out) {
    int idx = blockIdx.x * 256 + threadIdx.x;    // over BB*NN*EN
    int c  = idx & (EN - 1);
    int ri = idx >> 4;
    int b  = ri >> 12;
    int i  = ri & (NN - 1);
    float a = 0.f, Z = 0.f;
#pragma unroll
    for (int sp = 0; sp < KS8; sp++) {
        size_t rb = ((size_t)(b * KS8 + sp) << 12) + i;
        a += g_paccl[rb * EN + c];
        Z += g_pZl[rb];
    }
    out[((size_t)b * NN + i) * EN + c] = eluf(a / Z);
}

// ---------------- launch ----------------
extern "C" void kernel_launch(void* const* d_in, const int* in_sizes, int n_in,
                              void* d_out, int out_size) {
    const float* fea = (const float*)d_in[0];   // [B,N,D]
    const float* adj = (const float*)d_in[1];   // [B,N,N]
    const float* Wh  = (const float*)d_in[2];   // [H,D,HID]
    const float* ah  = (const float*)d_in[3];   // [H,2*HID,1]
    const float* Wl  = (const float*)d_in[4];   // [H*HID,EN]
    const float* al  = (const float*)d_in[5];   // [2*EN,1]
    float* out = (float*)d_out;                 // [B,N,EN]

    (void)in_sizes; (void)n_in; (void)out_size;

    k0_pack<<<(BB * NN) / 8, 256>>>(adj);
    k1_wh  <<<(BB * HH * NN) / 8, 256>>>(fea, Wh, ah);
    k2t    <<<dim3(NN / 64, NSP2, BB * HH), 128>>>();
    k2_comb<<<(BB * HH * NN * HID) / 256, 256>>>();
    k3_whl <<<(BB * NN) / 8, 256>>>(Wl, al);
    k4t    <<<dim3(NN / 64, KS8, BB), 128>>>();
    k4_comb<<<(BB * NN * EN) / 256, 256>>>(out);
}

// round 16
// speedup vs baseline: 1.7035x; 1.0510x over previous
#include <cuda_runtime.h>
#include <cstdint>

// Problem constants (fixed by reference)
#define BB   2
#define NN   4096
#define DD   128
#define HH   4
#define HID  32
#define EN   16

#define WPR  (NN/32)       // 128 mask words per row
#define CH   64            // j-chunk staged per iteration
#define NSP2 2             // j-splits, heads attention
#define KS8  8             // j-splits, last attention
#define PAD2 40            // row pad (words) heads tile  -> conflict-free B LDS
#define PAD4 24            // row pad (words) last tile

#define L2E    1.4426950408889634f    // log2(e)
#define P2L2E  0.28853900817779267f   // 0.2*log2(e)

// ---------------- scratch (device globals) ----------------
__device__ __align__(16) unsigned g_bits[(size_t)BB*NN*WPR];
__device__ __align__(16) float  g_wh  [BB*HH*NN*HID];
__device__ __align__(16) float2 g_w1e [BB*HH*NN];     // (exp(wh1), exp(.2 wh1))
__device__ __align__(16) float2 g_w2e [BB*HH*NN];     // (exp(wh2), exp(.2 wh2))
__device__ __align__(16) float  g_whl [BB*NN*EN];
__device__ __align__(16) float2 g_w1le[BB*NN];
__device__ __align__(16) float2 g_w2le[BB*NN];
__device__ __align__(16) float  g_pacc[(size_t)BB*HH*NSP2*NN*HID];
__device__ __align__(16) float  g_pZ  [BB*HH*NSP2*NN];
__device__ __align__(16) float  g_paccl[(size_t)BB*KS8*NN*EN];
__device__ __align__(16) float  g_pZl [BB*KS8*NN];

// ---------------- helpers ----------------
__device__ __forceinline__ float eluf(float x) { return x > 0.f ? x : expm1f(x); }
__device__ __forceinline__ float ex2f(float x) {
    float r; asm("ex2.approx.ftz.f32 %0,%1;" : "=f"(r) : "f"(x)); return r;
}
__device__ __forceinline__ uint32_t tf32r(float f) {
    uint32_t r; asm("cvt.rna.tf32.f32 %0,%1;" : "=r"(r) : "f"(f)); return r;
}
__device__ __forceinline__ void mma8(float* c, uint32_t a0, uint32_t a1, uint32_t a2, uint32_t a3,
                                     uint32_t b0, uint32_t b1) {
    asm volatile(
        "mma.sync.aligned.m16n8k8.row.col.f32.tf32.tf32.f32 "
        "{%0,%1,%2,%3},{%4,%5,%6,%7},{%8,%9},{%0,%1,%2,%3};"
        : "+f"(c[0]), "+f"(c[1]), "+f"(c[2]), "+f"(c[3])
        : "r"(a0), "r"(a1), "r"(a2), "r"(a3), "r"(b0), "r"(b1));
}

// ---------------- K0: pack adj into bitmask (read adj once) ----------------
__global__ void k0_pack(const float* __restrict__ adj) {
    int warp = (blockIdx.x * blockDim.x + threadIdx.x) >> 5;
    int lane = threadIdx.x & 31;
    const float* row = adj + (size_t)warp * NN;
    unsigned* dst = g_bits + (size_t)warp * WPR;
#pragma unroll 4
    for (int w = 0; w < WPR; w++) {
        float v = row[w * 32 + lane];
        unsigned b = __ballot_sync(0xffffffffu, v != 0.f);
        if (lane == 0) dst[w] = b;
    }
}

// ---------------- K1: wh = fea @ W_h ; exp pairs of wh1/wh2 ----------------
__global__ void k1_wh(const float* __restrict__ fea,
                      const float* __restrict__ Wh,
                      const float* __restrict__ ah) {
    int warp = (blockIdx.x * blockDim.x + threadIdx.x) >> 5;
    int lane = threadIdx.x & 31;
    int i  = warp & (NN - 1);
    int bh = warp >> 12;
    int b = bh >> 2, h = bh & 3;

    const float* xrow = fea + ((size_t)b * NN + i) * DD;
    const float* Wp   = Wh + (size_t)h * DD * HID + lane;

    float a0 = 0.f, a1 = 0.f, a2 = 0.f, a3 = 0.f;
#pragma unroll
    for (int k = 0; k < DD; k += 4) {
        float4 xv = *reinterpret_cast<const float4*>(xrow + k);
        a0 += xv.x * Wp[(k + 0) * HID];
        a1 += xv.y * Wp[(k + 1) * HID];
        a2 += xv.z * Wp[(k + 2) * HID];
        a3 += xv.w * Wp[(k + 3) * HID];
    }
    float acc = (a0 + a1) + (a2 + a3);
    g_wh[((size_t)bh * NN + i) * HID + lane] = acc;

    float v1 = acc * ah[h * 2 * HID + lane];
    float v2 = acc * ah[h * 2 * HID + HID + lane];
#pragma unroll
    for (int off = 16; off; off >>= 1) {
        v1 += __shfl_xor_sync(0xffffffffu, v1, off);
        v2 += __shfl_xor_sync(0xffffffffu, v2, off);
    }
    if (lane == 0) {
        g_w1e[bh * NN + i] = make_float2(ex2f(L2E * v1), ex2f(P2L2E * v1));
        g_w2e[bh * NN + i] = make_float2(ex2f(L2E * v2), ex2f(P2L2E * v2));
    }
}

// ---------------- K2: heads attention, warp mma, exp-product P-gen ----------------
// 128 threads = 4 warps x 16 rows = 64 rows/block; 2048 j per block.
__global__ __launch_bounds__(128, 7) void k2t() {
    __shared__ uint32_t whs[2][CH * PAD2];
    __shared__ float2 w2s[2][CH];

    int t = threadIdx.x, lane = t & 31, w = t >> 5;
    int bh = blockIdx.z, b = bh >> 2;
    int sp = blockIdx.y;
    int i0 = blockIdx.x * 64;
    int jbase = sp * (NN / NSP2);
    int row_lo = i0 + w * 16 + (lane >> 2);
    int qid = lane & 3, nn = lane >> 2;

    float2 Aa_lo = g_w1e[bh * NN + row_lo];
    float2 Aa_hi = g_w1e[bh * NN + row_lo + 8];
    const unsigned* bits_lo = g_bits + (size_t)(b * NN + row_lo) * WPR;
    const unsigned* bits_hi = bits_lo + 8 * WPR;
    const float* whp   = g_wh + (size_t)bh * NN * HID;
    const float2* w2e  = g_w2e + bh * NN;

    float C[4][4] = {};
    float zlo = 0.f, zhi = 0.f;

    float4 rv[4];
    float2 rw2 = make_float2(0.f, 0.f);
    unsigned nml0, nml1, nmh0, nmh1;

    {   // load chunk 0
        int j0 = jbase;
#pragma unroll
        for (int k = 0; k < 4; k++) {
            int f = t + k * 128, jj = f >> 3, c4 = (f & 7) * 4;
            rv[k] = *reinterpret_cast<const float4*>(whp + (size_t)(j0 + jj) * HID + c4);
        }
        if (t < CH) rw2 = w2e[j0 + t];
        int jw = j0 >> 5;
        nml0 = bits_lo[jw]; nml1 = bits_lo[jw + 1];
        nmh0 = bits_hi[jw]; nmh1 = bits_hi[jw + 1];
    }

    const int NCH = (NN / NSP2) / CH;        // 32
    for (int c = 0; c < NCH; c++) {
        int buf = c & 1;
        // store staged tile
#pragma unroll
        for (int k = 0; k < 4; k++) {
            int f = t + k * 128, jj = f >> 3, c4 = (f & 7) * 4;
            uint4 u;
            u.x = tf32r(rv[k].x); u.y = tf32r(rv[k].y);
            u.z = tf32r(rv[k].z); u.w = tf32r(rv[k].w);
            *reinterpret_cast<uint4*>(&whs[buf][jj * PAD2 + c4]) = u;
        }
        if (t < CH) w2s[buf][t] = rw2;
        unsigned ml0 = nml0, ml1 = nml1, mh0 = nmh0, mh1 = nmh1;
        __syncthreads();                      // single barrier per chunk

        if (c + 1 < NCH) {                    // prefetch next chunk
            int j0 = jbase + (c + 1) * CH;
#pragma unroll
            for (int k = 0; k < 4; k++) {
                int f = t + k * 128, jj = f >> 3, c4 = (f & 7) * 4;
                rv[k] = *reinterpret_cast<const float4*>(whp + (size_t)(j0 + jj) * HID + c4);
            }
            if (t < CH) rw2 = w2e[j0 + t];
            int jw = j0 >> 5;
            nml0 = bits_lo[jw]; nml1 = bits_lo[jw + 1];
            nmh0 = bits_hi[jw]; nmh1 = bits_hi[jw + 1];
        }

#pragma unroll
        for (int kc = 0; kc < CH / 8; kc++) {
            unsigned wlo = (kc < 4) ? ml0 : ml1;
            unsigned whi = (kc < 4) ? mh0 : mh1;
            int sh = (kc * 8 + qid) & 31;
            unsigned blo = wlo >> sh, bhi = whi >> sh;
            float2 eja = w2s[buf][kc * 8 + qid];
            float2 ejb = w2s[buf][kc * 8 + qid + 4];

            // p = max(exp(wh1)exp(wh2), exp(.2wh1)exp(.2wh2)) = exp(leakyrelu(s))
            float pe0 = fmaxf(Aa_lo.x * eja.x, Aa_lo.y * eja.y);
            float pe1 = fmaxf(Aa_hi.x * eja.x, Aa_hi.y * eja.y);
            float pe2 = fmaxf(Aa_lo.x * ejb.x, Aa_lo.y * ejb.y);
            float pe3 = fmaxf(Aa_hi.x * ejb.x, Aa_hi.y * ejb.y);
            float p0 = (blo & 1u)  ? pe0 : 0.f;
            float p1 = (bhi & 1u)  ? pe1 : 0.f;
            float p2 = (blo & 16u) ? pe2 : 0.f;
            float p3 = (bhi & 16u) ? pe3 : 0.f;
            zlo += p0 + p2; zhi += p1 + p3;
            uint32_t a0 = tf32r(p0), a1 = tf32r(p1), a2 = tf32r(p2), a3 = tf32r(p3);

            const uint32_t* b0p = &whs[buf][(kc * 8 + qid) * PAD2 + nn];
            const uint32_t* b1p = b0p + 4 * PAD2;
#pragma unroll
            for (int nt = 0; nt < 4; nt++)
                mma8(C[nt], a0, a1, a2, a3, b0p[nt * 8], b1p[nt * 8]);
        }
    }

    zlo += __shfl_xor_sync(0xffffffffu, zlo, 1);
    zlo += __shfl_xor_sync(0xffffffffu, zlo, 2);
    zhi += __shfl_xor_sync(0xffffffffu, zhi, 1);
    zhi += __shfl_xor_sync(0xffffffffu, zhi, 2);

    size_t rb = (size_t)((bh * NSP2 + sp) * NN + row_lo);
    float* dlo = g_pacc + rb * HID + qid * 2;
    float* dhi = g_pacc + (rb + 8) * HID + qid * 2;
#pragma unroll
    for (int nt = 0; nt < 4; nt++) {
        *reinterpret_cast<float2*>(dlo + nt * 8) = make_float2(C[nt][0], C[nt][1]);
        *reinterpret_cast<float2*>(dhi + nt * 8) = make_float2(C[nt][2], C[nt][3]);
    }
    if (qid == 0) { g_pZ[rb] = zlo; g_pZ[rb + 8] = zhi; }
}

// ---------------- K3f: fused combine+ELU+GEMM ; exp pairs of wh1l/wh2l ----------------
// warp per (b,row); phase1 builds the xcat row in SMEM, phase2 does the GEMM.
__global__ __launch_bounds__(256) void k3f(const float* __restrict__ Wl, const float* __restrict__ al) {
    __shared__ float Wls[128 * EN];
    __shared__ float als[2 * EN];
    __shared__ float xs[8][128];
    int t = threadIdx.x;
#pragma unroll
    for (int u = 0; u < 8; u++) Wls[t + u * 256] = Wl[t + u * 256];
    if (t < 2 * EN) als[t] = al[t];
    __syncthreads();

    int warp = (blockIdx.x * 256 + t) >> 5;
    int lane = t & 31, w = t >> 5;
    int b = warp >> 12, i = warp & (NN - 1);

    // phase 1: combine splits, divide, ELU -> xs[w][lane*4 .. +3]
    {
        int el = lane * 4;
        int h  = el >> 5;                      // head
        int cc = el & 31;
        size_t rb0 = ((size_t)((b * HH + h) * NSP2) * NN + i);
        float Zh = g_pZ[rb0] + g_pZ[rb0 + NN];
        float inv = 1.f / Zh;
        float4 u0 = *reinterpret_cast<const float4*>(g_pacc + rb0 * HID + cc);
        float4 u1 = *reinterpret_cast<const float4*>(g_pacc + (rb0 + NN) * HID + cc);
        float4 xv;
        xv.x = eluf((u0.x + u1.x) * inv);
        xv.y = eluf((u0.y + u1.y) * inv);
        xv.z = eluf((u0.z + u1.z) * inv);
        xv.w = eluf((u0.w + u1.w) * inv);
        *reinterpret_cast<float4*>(&xs[w][el]) = xv;
    }
    __syncwarp();

    // phase 2: GEMM row x W_last
    int c = lane & 15, half = lane >> 4;
    const float* Wp = Wls + half * 64 * EN + c;
    float a0 = 0.f, a1 = 0.f;
#pragma unroll
    for (int k = 0; k < 64; k += 4) {
        float4 xv = *reinterpret_cast<const float4*>(&xs[w][half * 64 + k]);
        a0 += xv.x * Wp[(k + 0) * EN];
        a1 += xv.y * Wp[(k + 1) * EN];
        a0 += xv.z * Wp[(k + 2) * EN];
        a1 += xv.w * Wp[(k + 3) * EN];
    }
    float acc = a0 + a1;
    acc += __shfl_xor_sync(0xffffffffu, acc, 16);
    if (half == 0) g_whl[((size_t)b * NN + i) * EN + c] = acc;

    float v1 = acc * als[c];
    float v2 = acc * als[EN + c];
#pragma unroll
    for (int off = 8; off; off >>= 1) {
        v1 += __shfl_xor_sync(0xffffffffu, v1, off);
        v2 += __shfl_xor_sync(0xffffffffu, v2, off);
    }
    if (lane == 0) {
        g_w1le[b * NN + i] = make_float2(ex2f(L2E * v1), ex2f(P2L2E * v1));
        g_w2le[b * NN + i] = make_float2(ex2f(L2E * v2), ex2f(P2L2E * v2));
    }
}

// ---------------- K4: last-layer attention, warp mma, exp-product P-gen ----------------
__global__ __launch_bounds__(128, 7) void k4t() {
    __shared__ uint32_t whs[2][CH * PAD4];
    __shared__ float2 w2s[2][CH];

    int t = threadIdx.x, lane = t & 31, w = t >> 5;
    int b  = blockIdx.z;
    int ks = blockIdx.y;
    int i0 = blockIdx.x * 64;
    int jbase = ks * (NN / KS8);             // 512 j per block
    int row_lo = i0 + w * 16 + (lane >> 2);
    int qid = lane & 3, nn = lane >> 2;

    float2 Aa_lo = g_w1le[b * NN + row_lo];
    float2 Aa_hi = g_w1le[b * NN + row_lo + 8];
    const unsigned* bits_lo = g_bits + (size_t)(b * NN + row_lo) * WPR;
    const unsigned* bits_hi = bits_lo + 8 * WPR;
    const float* whp  = g_whl + (size_t)b * NN * EN;
    const float2* w2e = g_w2le + b * NN;

    float C[2][4] = {};
    float zlo = 0.f, zhi = 0.f;

    float4 rv[2];
    float2 rw2 = make_float2(0.f, 0.f);
    unsigned nml0, nml1, nmh0, nmh1;

    {
        int j0 = jbase;
#pragma unroll
        for (int k = 0; k < 2; k++) {
            int f = t + k * 128, jj = f >> 2, c4 = (f & 3) * 4;
            rv[k] = *reinterpret_cast<const float4*>(whp + (size_t)(j0 + jj) * EN + c4);
        }
        if (t < CH) rw2 = w2e[j0 + t];
        int jw = j0 >> 5;
        nml0 = bits_lo[jw]; nml1 = bits_lo[jw + 1];
        nmh0 = bits_hi[jw]; nmh1 = bits_hi[jw + 1];
    }

    const int NCH = (NN / KS8) / CH;         // 8
    for (int c = 0; c < NCH; c++) {
        int buf = c & 1;
#pragma unroll
        for (int k = 0; k < 2; k++) {
            int f = t + k * 128, jj = f >> 2, c4 = (f & 3) * 4;
            uint4 u;
            u.x = tf32r(rv[k].x); u.y = tf32r(rv[k].y);
            u.z = tf32r(rv[k].z); u.w = tf32r(rv[k].w);
            *reinterpret_cast<uint4*>(&whs[buf][jj * PAD4 + c4]) = u;
        }
        if (t < CH) w2s[buf][t] = rw2;
        unsigned ml0 = nml0, ml1 = nml1, mh0 = nmh0, mh1 = nmh1;
        __syncthreads();

        if (c + 1 < NCH) {
            int j0 = jbase + (c + 1) * CH;
#pragma unroll
            for (int k = 0; k < 2; k++) {
                int f = t + k * 128, jj = f >> 2, c4 = (f & 3) * 4;
                rv[k] = *reinterpret_cast<const float4*>(whp + (size_t)(j0 + jj) * EN + c4);
            }
            if (t < CH) rw2 = w2e[j0 + t];
            int jw = j0 >> 5;
            nml0 = bits_lo[jw]; nml1 = bits_lo[jw + 1];
            nmh0 = bits_hi[jw]; nmh1 = bits_hi[jw + 1];
        }

#pragma unroll
        for (int kc = 0; kc < CH / 8; kc++) {
            unsigned wlo = (kc < 4) ? ml0 : ml1;
            unsigned whi = (kc < 4) ? mh0 : mh1;
            int sh = (kc * 8 + qid) & 31;
            unsigned blo = wlo >> sh, bhi = whi >> sh;
            float2 eja = w2s[buf][kc * 8 + qid];
            float2 ejb = w2s[buf][kc * 8 + qid + 4];

            float pe0 = fmaxf(Aa_lo.x * eja.x, Aa_lo.y * eja.y);
            float pe1 = fmaxf(Aa_hi.x * eja.x, Aa_hi.y * eja.y);
            float pe2 = fmaxf(Aa_lo.x * ejb.x, Aa_lo.y * ejb.y);
            float pe3 = fmaxf(Aa_hi.x * ejb.x, Aa_hi.y * ejb.y);
            float p0 = (blo & 1u)  ? pe0 : 0.f;
            float p1 = (bhi & 1u)  ? pe1 : 0.f;
            float p2 = (blo & 16u) ? pe2 : 0.f;
            float p3 = (bhi & 16u) ? pe3 : 0.f;
            zlo += p0 + p2; zhi += p1 + p3;
            uint32_t a0 = tf32r(p0), a1 = tf32r(p1), a2 = tf32r(p2), a3 = tf32r(p3);

            const uint32_t* b0p = &whs[buf][(kc * 8 + qid) * PAD4 + nn];
            const uint32_t* b1p = b0p + 4 * PAD4;
#pragma unroll
            for (int nt = 0; nt < 2; nt++)
                mma8(C[nt], a0, a1, a2, a3, b0p[nt * 8], b1p[nt * 8]);
        }
    }

    zlo += __shfl_xor_sync(0xffffffffu, zlo, 1);
    zlo += __shfl_xor_sync(0xffffffffu, zlo, 2);
    zhi += __shfl_xor_sync(0xffffffffu, zhi, 1);
    zhi += __shfl_xor_sync(0xffffffffu, zhi, 2);

    size_t rb = (size_t)((b * KS8 + ks) * NN + row_lo);
    float* dlo = g_paccl + rb * EN + qid * 2;
    float* dhi = g_paccl + (rb + 8) * EN + qid * 2;
#pragma unroll
    for (int nt = 0; nt < 2; nt++) {
        *reinterpret_cast<float2*>(dlo + nt * 8) = make_float2(C[nt][0], C[nt][1]);
        *reinterpret_cast<float2*>(dhi + nt * 8) = make_float2(C[nt][2], C[nt][3]);
    }
    if (qid == 0) { g_pZl[rb] = zlo; g_pZl[rb + 8] = zhi; }
}

// ---------------- K4b: combine splits, divide, ELU, write output ----------------
__global__ void k4_comb(float* __restrict__ out) {
    int idx = blockIdx.x * 256 + threadIdx.x;    // over BB*NN*EN
    int c  = idx & (EN - 1);
    int ri = idx >> 4;
    int b  = ri >> 12;
    int i  = ri & (NN - 1);
    float a = 0.f, Z = 0.f;
#pragma unroll
    for (int sp = 0; sp < KS8; sp++) {
        size_t rb = ((size_t)(b * KS8 + sp) << 12) + i;
        a += g_paccl[rb * EN + c];
        Z += g_pZl[rb];
    }
    out[((size_t)b * NN + i) * EN + c] = eluf(a / Z);
}

// ---------------- launch ----------------
extern "C" void kernel_launch(void* const* d_in, const int* in_sizes, int n_in,
                              void* d_out, int out_size) {
    const float* fea = (const float*)d_in[0];   // [B,N,D]
    const float* adj = (const float*)d_in[1];   // [B,N,N]
    const float* Wh  = (const float*)d_in[2];   // [H,D,HID]
    const float* ah  = (const float*)d_in[3];   // [H,2*HID,1]
    const float* Wl  = (const float*)d_in[4];   // [H*HID,EN]
    const float* al  = (const float*)d_in[5];   // [2*EN,1]
    float* out = (float*)d_out;                 // [B,N,EN]

    (void)in_sizes; (void)n_in; (void)out_size;

    k0_pack<<<(BB * NN) / 8, 256>>>(adj);
    k1_wh  <<<(BB * HH * NN) / 8, 256>>>(fea, Wh, ah);
    k2t    <<<dim3(NN / 64, NSP2, BB * HH), 128>>>();
    k3f    <<<(BB * NN) / 8, 256>>>(Wl, al);
    k4t    <<<dim3(NN / 64, KS8, BB), 128>>>();
    k4_comb<<<(BB * NN * EN) / 256, 256>>>(out);
}

// round 17
// speedup vs baseline: 2.1345x; 1.2530x over previous
#include <cuda_runtime.h>
#include <cstdint>

// Problem constants (fixed by reference)
#define BB   2
#define NN   4096
#define DD   128
#define HH   4
#define HID  32
#define EN   16

#define WPR  (NN/32)       // 128 mask words per row
#define CH   64            // j-chunk staged per iteration
#define NSP2 2             // j-splits, heads attention
#define KS8  8             // j-splits, last attention
#define PAD2 40            // row pad (words), heads B tile (32 data words/row)
#define PAD4 24            // row pad (words), last B tile  (16 data words/row)

#define L2E    1.4426950408889634f    // log2(e)
#define P2L2E  0.28853900817779267f   // 0.2*log2(e)

// ---------------- scratch (device globals) ----------------
__device__ __align__(16) unsigned g_bits[(size_t)BB*NN*WPR];
__device__ __align__(16) float  g_wh  [BB*HH*NN*HID];
__device__ __align__(16) float2 g_w1e [BB*HH*NN];     // (exp(wh1), exp(.2 wh1))
__device__ __align__(16) float2 g_w2e [BB*HH*NN];     // (exp(wh2), exp(.2 wh2))
__device__ __align__(16) float  g_whl [BB*NN*EN];
__device__ __align__(16) float2 g_w1le[BB*NN];
__device__ __align__(16) float2 g_w2le[BB*NN];
__device__ __align__(16) float  g_pacc[(size_t)BB*HH*NSP2*NN*HID];
__device__ __align__(16) float  g_pZ  [BB*HH*NSP2*NN];
__device__ __align__(16) float  g_paccl[(size_t)BB*KS8*NN*EN];
__device__ __align__(16) float  g_pZl [BB*KS8*NN];

// ---------------- helpers ----------------
__device__ __forceinline__ float eluf(float x) { return x > 0.f ? x : expm1f(x); }
__device__ __forceinline__ float ex2f(float x) {
    float r; asm("ex2.approx.ftz.f32 %0,%1;" : "=f"(r) : "f"(x)); return r;
}
__device__ __forceinline__ uint32_t bf2(float hi, float lo) {   // {lo | hi<<16}
    uint32_t d; asm("cvt.rn.bf16x2.f32 %0,%1,%2;" : "=r"(d) : "f"(hi), "f"(lo)); return d;
}
// portable warp MMA: D(16x8) += A(16x16,bf16) * B(16x8,bf16)
__device__ __forceinline__ void mma16(float* c, uint32_t a0, uint32_t a1, uint32_t a2, uint32_t a3,
                                      uint32_t b0, uint32_t b1) {
    asm volatile(
        "mma.sync.aligned.m16n8k16.row.col.f32.bf16.bf16.f32 "
        "{%0,%1,%2,%3},{%4,%5,%6,%7},{%8,%9},{%0,%1,%2,%3};"
        : "+f"(c[0]), "+f"(c[1]), "+f"(c[2]), "+f"(c[3])
        : "r"(a0), "r"(a1), "r"(a2), "r"(a3), "r"(b0), "r"(b1));
}

// ---------------- K0: pack adj into bitmask (read adj once) ----------------
__global__ void k0_pack(const float* __restrict__ adj) {
    int warp = (blockIdx.x * blockDim.x + threadIdx.x) >> 5;
    int lane = threadIdx.x & 31;
    const float* row = adj + (size_t)warp * NN;
    unsigned* dst = g_bits + (size_t)warp * WPR;
#pragma unroll 4
    for (int w = 0; w < WPR; w++) {
        float v = row[w * 32 + lane];
        unsigned b = __ballot_sync(0xffffffffu, v != 0.f);
        if (lane == 0) dst[w] = b;
    }
}

// ---------------- K1: wh = fea @ W_h ; exp pairs of wh1/wh2 ----------------
__global__ void k1_wh(const float* __restrict__ fea,
                      const float* __restrict__ Wh,
                      const float* __restrict__ ah) {
    int warp = (blockIdx.x * blockDim.x + threadIdx.x) >> 5;
    int lane = threadIdx.x & 31;
    int i  = warp & (NN - 1);
    int bh = warp >> 12;
    int b = bh >> 2, h = bh & 3;

    const float* xrow = fea + ((size_t)b * NN + i) * DD;
    const float* Wp   = Wh + (size_t)h * DD * HID + lane;

    float a0 = 0.f, a1 = 0.f, a2 = 0.f, a3 = 0.f;
#pragma unroll
    for (int k = 0; k < DD; k += 4) {
        float4 xv = *reinterpret_cast<const float4*>(xrow + k);
        a0 += xv.x * Wp[(k + 0) * HID];
        a1 += xv.y * Wp[(k + 1) * HID];
        a2 += xv.z * Wp[(k + 2) * HID];
        a3 += xv.w * Wp[(k + 3) * HID];
    }
    float acc = (a0 + a1) + (a2 + a3);
    g_wh[((size_t)bh * NN + i) * HID + lane] = acc;

    float v1 = acc * ah[h * 2 * HID + lane];
    float v2 = acc * ah[h * 2 * HID + HID + lane];
#pragma unroll
    for (int off = 16; off; off >>= 1) {
        v1 += __shfl_xor_sync(0xffffffffu, v1, off);
        v2 += __shfl_xor_sync(0xffffffffu, v2, off);
    }
    if (lane == 0) {
        g_w1e[bh * NN + i] = make_float2(ex2f(L2E * v1), ex2f(P2L2E * v1));
        g_w2e[bh * NN + i] = make_float2(ex2f(L2E * v2), ex2f(P2L2E * v2));
    }
}

// ---------------- K2: heads attention, bf16 m16n8k16 warp mma ----------------
// 128 threads = 4 warps x 16 rows = 64 rows/block; 2048 j per block.
// B tile stored as bf16x2 words: W[jp][n] = {wh[2jp][n] lo, wh[2jp+1][n] hi}
__global__ __launch_bounds__(128, 7) void k2t() {
    __shared__ uint32_t whs[2][32 * PAD2];
    __shared__ float2 w2s[2][CH];

    int t = threadIdx.x, lane = t & 31, w = t >> 5;
    int bh = blockIdx.z, b = bh >> 2;
    int sp = blockIdx.y;
    int i0 = blockIdx.x * 64;
    int jbase = sp * (NN / NSP2);
    int row_lo = i0 + w * 16 + (lane >> 2);
    int qid = lane & 3, nn = lane >> 2;

    float2 Aa_lo = g_w1e[bh * NN + row_lo];
    float2 Aa_hi = g_w1e[bh * NN + row_lo + 8];
    const unsigned* bits_lo = g_bits + (size_t)(b * NN + row_lo) * WPR;
    const unsigned* bits_hi = bits_lo + 8 * WPR;
    const float* whp   = g_wh + (size_t)bh * NN * HID;
    const float2* w2e  = g_w2e + bh * NN;

    float C[4][4] = {};
    float zlo = 0.f, zhi = 0.f;

    uint4 ru[2];                      // prefetched tile, already bf16x2-packed
    float2 rw2 = make_float2(0.f, 0.f);
    unsigned nml0, nml1, nmh0, nmh1;

    {   // load+convert chunk 0
        int j0 = jbase;
#pragma unroll
        for (int k = 0; k < 2; k++) {
            int f = t + k * 128, jp = f >> 3, grp = f & 7;
            const float* p0 = whp + (size_t)(j0 + 2 * jp) * HID + grp * 4;
            float4 v0 = *reinterpret_cast<const float4*>(p0);
            float4 v1 = *reinterpret_cast<const float4*>(p0 + HID);
            ru[k].x = bf2(v1.x, v0.x); ru[k].y = bf2(v1.y, v0.y);
            ru[k].z = bf2(v1.z, v0.z); ru[k].w = bf2(v1.w, v0.w);
        }
        if (t < CH) rw2 = w2e[j0 + t];
        int jw = j0 >> 5;
        nml0 = bits_lo[jw]; nml1 = bits_lo[jw + 1];
        nmh0 = bits_hi[jw]; nmh1 = bits_hi[jw + 1];
    }

    const int NCH = (NN / NSP2) / CH;        // 32
    for (int c = 0; c < NCH; c++) {
        int buf = c & 1;
#pragma unroll
        for (int k = 0; k < 2; k++) {
            int f = t + k * 128, jp = f >> 3, grp = f & 7;
            *reinterpret_cast<uint4*>(&whs[buf][jp * PAD2 + grp * 4]) = ru[k];
        }
        if (t < CH) w2s[buf][t] = rw2;
        unsigned ml0 = nml0, ml1 = nml1, mh0 = nmh0, mh1 = nmh1;
        __syncthreads();

        if (c + 1 < NCH) {                    // prefetch+convert next chunk
            int j0 = jbase + (c + 1) * CH;
#pragma unroll
            for (int k = 0; k < 2; k++) {
                int f = t + k * 128, jp = f >> 3, grp = f & 7;
                const float* p0 = whp + (size_t)(j0 + 2 * jp) * HID + grp * 4;
                float4 v0 = *reinterpret_cast<const float4*>(p0);
                float4 v1 = *reinterpret_cast<const float4*>(p0 + HID);
                ru[k].x = bf2(v1.x, v0.x); ru[k].y = bf2(v1.y, v0.y);
                ru[k].z = bf2(v1.z, v0.z); ru[k].w = bf2(v1.w, v0.w);
            }
            if (t < CH) rw2 = w2e[j0 + t];
            int jw = j0 >> 5;
            nml0 = bits_lo[jw]; nml1 = bits_lo[jw + 1];
            nmh0 = bits_hi[jw]; nmh1 = bits_hi[jw + 1];
        }

#pragma unroll
        for (int kc = 0; kc < 4; kc++) {      // 16 j per kc
            unsigned wl = (kc < 2) ? ml0 : ml1;
            unsigned wh_ = (kc < 2) ? mh0 : mh1;
            int sh = ((kc & 1) << 4) + 2 * qid;
            unsigned ulo = wl >> sh, uhi = wh_ >> sh;
            // e pairs for j = kc*16 + {2q,2q+1} and {2q+8,2q+9}
            float4 ea = *reinterpret_cast<const float4*>(&w2s[buf][kc * 16 + 2 * qid]);
            float4 eb = *reinterpret_cast<const float4*>(&w2s[buf][kc * 16 + 2 * qid + 8]);

            float pl0 = (ulo & 1u)   ? fmaxf(Aa_lo.x * ea.x, Aa_lo.y * ea.y) : 0.f;
            float pl1 = (ulo & 2u)   ? fmaxf(Aa_lo.x * ea.z, Aa_lo.y * ea.w) : 0.f;
            float ph0 = (uhi & 1u)   ? fmaxf(Aa_hi.x * ea.x, Aa_hi.y * ea.y) : 0.f;
            float ph1 = (uhi & 2u)   ? fmaxf(Aa_hi.x * ea.z, Aa_hi.y * ea.w) : 0.f;
            float pl8 = (ulo & 256u) ? fmaxf(Aa_lo.x * eb.x, Aa_lo.y * eb.y) : 0.f;
            float pl9 = (ulo & 512u) ? fmaxf(Aa_lo.x * eb.z, Aa_lo.y * eb.w) : 0.f;
            float ph8 = (uhi & 256u) ? fmaxf(Aa_hi.x * eb.x, Aa_hi.y * eb.y) : 0.f;
            float ph9 = (uhi & 512u) ? fmaxf(Aa_hi.x * eb.z, Aa_hi.y * eb.w) : 0.f;
            zlo += (pl0 + pl1) + (pl8 + pl9);
            zhi += (ph0 + ph1) + (ph8 + ph9);

            uint32_t a0 = bf2(pl1, pl0), a1 = bf2(ph1, ph0);
            uint32_t a2 = bf2(pl9, pl8), a3 = bf2(ph9, ph8);

            const uint32_t* brow = &whs[buf][(kc * 8 + qid) * PAD2 + nn];
#pragma unroll
            for (int nt = 0; nt < 4; nt++)
                mma16(C[nt], a0, a1, a2, a3, brow[nt * 8], brow[4 * PAD2 + nt * 8]);
        }
    }

    zlo += __shfl_xor_sync(0xffffffffu, zlo, 1);
    zlo += __shfl_xor_sync(0xffffffffu, zlo, 2);
    zhi += __shfl_xor_sync(0xffffffffu, zhi, 1);
    zhi += __shfl_xor_sync(0xffffffffu, zhi, 2);

    size_t rb = (size_t)((bh * NSP2 + sp) * NN + row_lo);
    float* dlo = g_pacc + rb * HID + qid * 2;
    float* dhi = g_pacc + (rb + 8) * HID + qid * 2;
#pragma unroll
    for (int nt = 0; nt < 4; nt++) {
        *reinterpret_cast<float2*>(dlo + nt * 8) = make_float2(C[nt][0], C[nt][1]);
        *reinterpret_cast<float2*>(dhi + nt * 8) = make_float2(C[nt][2], C[nt][3]);
    }
    if (qid == 0) { g_pZ[rb] = zlo; g_pZ[rb + 8] = zhi; }
}

// ---------------- K3f: fused combine+ELU+GEMM ; exp pairs of wh1l/wh2l ----------------
__global__ __launch_bounds__(256) void k3f(const float* __restrict__ Wl, const float* __restrict__ al) {
    __shared__ float Wls[128 * EN];
    __shared__ float als[2 * EN];
    __shared__ float xs[8][128];
    int t = threadIdx.x;
#pragma unroll
    for (int u = 0; u < 8; u++) Wls[t + u * 256] = Wl[t + u * 256];
    if (t < 2 * EN) als[t] = al[t];
    __syncthreads();

    int warp = (blockIdx.x * 256 + t) >> 5;
    int lane = t & 31, w = t >> 5;
    int b = warp >> 12, i = warp & (NN - 1);

    {   // combine splits, divide, ELU
        int el = lane * 4;
        int h  = el >> 5;
        int cc = el & 31;
        size_t rb0 = ((size_t)((b * HH + h) * NSP2) * NN + i);
        float Zh = g_pZ[rb0] + g_pZ[rb0 + NN];
        float inv = 1.f / Zh;
        float4 u0 = *reinterpret_cast<const float4*>(g_pacc + rb0 * HID + cc);
        float4 u1 = *reinterpret_cast<const float4*>(g_pacc + (rb0 + NN) * HID + cc);
        float4 xv;
        xv.x = eluf((u0.x + u1.x) * inv);
        xv.y = eluf((u0.y + u1.y) * inv);
        xv.z = eluf((u0.z + u1.z) * inv);
        xv.w = eluf((u0.w + u1.w) * inv);
        *reinterpret_cast<float4*>(&xs[w][el]) = xv;
    }
    __syncwarp();

    int c = lane & 15, half = lane >> 4;
    const float* Wp = Wls + half * 64 * EN + c;
    float a0 = 0.f, a1 = 0.f;
#pragma unroll
    for (int k = 0; k < 64; k += 4) {
        float4 xv = *reinterpret_cast<const float4*>(&xs[w][half * 64 + k]);
        a0 += xv.x * Wp[(k + 0) * EN];
        a1 += xv.y * Wp[(k + 1) * EN];
        a0 += xv.z * Wp[(k + 2) * EN];
        a1 += xv.w * Wp[(k + 3) * EN];
    }
    float acc = a0 + a1;
    acc += __shfl_xor_sync(0xffffffffu, acc, 16);
    if (half == 0) g_whl[((size_t)b * NN + i) * EN + c] = acc;

    float v1 = acc * als[c];
    float v2 = acc * als[EN + c];
#pragma unroll
    for (int off = 8; off; off >>= 1) {
        v1 += __shfl_xor_sync(0xffffffffu, v1, off);
        v2 += __shfl_xor_sync(0xffffffffu, v2, off);
    }
    if (lane == 0) {
        g_w1le[b * NN + i] = make_float2(ex2f(L2E * v1), ex2f(P2L2E * v1));
        g_w2le[b * NN + i] = make_float2(ex2f(L2E * v2), ex2f(P2L2E * v2));
    }
}

// ---------------- K4: last-layer attention, bf16 m16n8k16, j-split x8 ----------------
__global__ __launch_bounds__(128, 7) void k4t() {
    __shared__ uint32_t whs[2][32 * PAD4];
    __shared__ float2 w2s[2][CH];

    int t = threadIdx.x, lane = t & 31, w = t >> 5;
    int b  = blockIdx.z;
    int ks = blockIdx.y;
    int i0 = blockIdx.x * 64;
    int jbase = ks * (NN / KS8);             // 512 j per block
    int row_lo = i0 + w * 16 + (lane >> 2);
    int qid = lane & 3, nn = lane >> 2;

    float2 Aa_lo = g_w1le[b * NN + row_lo];
    float2 Aa_hi = g_w1le[b * NN + row_lo + 8];
    const unsigned* bits_lo = g_bits + (size_t)(b * NN + row_lo) * WPR;
    const unsigned* bits_hi = bits_lo + 8 * WPR;
    const float* whp  = g_whl + (size_t)b * NN * EN;
    const float2* w2e = g_w2le + b * NN;

    float C[2][4] = {};
    float zlo = 0.f, zhi = 0.f;

    uint4 ru;
    float2 rw2 = make_float2(0.f, 0.f);
    unsigned nml0, nml1, nmh0, nmh1;

    {
        int j0 = jbase;
        int jp = t >> 2, grp = t & 3;
        const float* p0 = whp + (size_t)(j0 + 2 * jp) * EN + grp * 4;
        float4 v0 = *reinterpret_cast<const float4*>(p0);
        float4 v1 = *reinterpret_cast<const float4*>(p0 + EN);
        ru.x = bf2(v1.x, v0.x); ru.y = bf2(v1.y, v0.y);
        ru.z = bf2(v1.z, v0.z); ru.w = bf2(v1.w, v0.w);
        if (t < CH) rw2 = w2e[j0 + t];
        int jw = j0 >> 5;
        nml0 = bits_lo[jw]; nml1 = bits_lo[jw + 1];
        nmh0 = bits_hi[jw]; nmh1 = bits_hi[jw + 1];
    }

    const int NCH = (NN / KS8) / CH;         // 8
    for (int c = 0; c < NCH; c++) {
        int buf = c & 1;
        {
            int jp = t >> 2, grp = t & 3;
            *reinterpret_cast<uint4*>(&whs[buf][jp * PAD4 + grp * 4]) = ru;
        }
        if (t < CH) w2s[buf][t] = rw2;
        unsigned ml0 = nml0, ml1 = nml1, mh0 = nmh0, mh1 = nmh1;
        __syncthreads();

        if (c + 1 < NCH) {
            int j0 = jbase + (c + 1) * CH;
            int jp = t >> 2, grp = t & 3;
            const float* p0 = whp + (size_t)(j0 + 2 * jp) * EN + grp * 4;
            float4 v0 = *reinterpret_cast<const float4*>(p0);
            float4 v1 = *reinterpret_cast<const float4*>(p0 + EN);
            ru.x = bf2(v1.x, v0.x); ru.y = bf2(v1.y, v0.y);
            ru.z = bf2(v1.z, v0.z); ru.w = bf2(v1.w, v0.w);
            if (t < CH) rw2 = w2e[j0 + t];
            int jw = j0 >> 5;
            nml0 = bits_lo[jw]; nml1 = bits_lo[jw + 1];
            nmh0 = bits_hi[jw]; nmh1 = bits_hi[jw + 1];
        }

#pragma unroll
        for (int kc = 0; kc < 4; kc++) {
            unsigned wl = (kc < 2) ? ml0 : ml1;
            unsigned wh_ = (kc < 2) ? mh0 : mh1;
            int sh = ((kc & 1) << 4) + 2 * qid;
            unsigned ulo = wl >> sh, uhi = wh_ >> sh;
            float4 ea = *reinterpret_cast<const float4*>(&w2s[buf][kc * 16 + 2 * qid]);
            float4 eb = *reinterpret_cast<const float4*>(&w2s[buf][kc * 16 + 2 * qid + 8]);

            float pl0 = (ulo & 1u)   ? fmaxf(Aa_lo.x * ea.x, Aa_lo.y * ea.y) : 0.f;
            float pl1 = (ulo & 2u)   ? fmaxf(Aa_lo.x * ea.z, Aa_lo.y * ea.w) : 0.f;
            float ph0 = (uhi & 1u)   ? fmaxf(Aa_hi.x * ea.x, Aa_hi.y * ea.y) : 0.f;
            float ph1 = (uhi & 2u)   ? fmaxf(Aa_hi.x * ea.z, Aa_hi.y * ea.w) : 0.f;
            float pl8 = (ulo & 256u) ? fmaxf(Aa_lo.x * eb.x, Aa_lo.y * eb.y) : 0.f;
            float pl9 = (ulo & 512u) ? fmaxf(Aa_lo.x * eb.z, Aa_lo.y * eb.w) : 0.f;
            float ph8 = (uhi & 256u) ? fmaxf(Aa_hi.x * eb.x, Aa_hi.y * eb.y) : 0.f;
            float ph9 = (uhi & 512u) ? fmaxf(Aa_hi.x * eb.z, Aa_hi.y * eb.w) : 0.f;
            zlo += (pl0 + pl1) + (pl8 + pl9);
            zhi += (ph0 + ph1) + (ph8 + ph9);

            uint32_t a0 = bf2(pl1, pl0), a1 = bf2(ph1, ph0);
            uint32_t a2 = bf2(pl9, pl8), a3 = bf2(ph9, ph8);

            const uint32_t* brow = &whs[buf][(kc * 8 + qid) * PAD4 + nn];
#pragma unroll
            for (int nt = 0; nt < 2; nt++)
                mma16(C[nt], a0, a1, a2, a3, brow[nt * 8], brow[4 * PAD4 + nt * 8]);
        }
    }

    zlo += __shfl_xor_sync(0xffffffffu, zlo, 1);
    zlo += __shfl_xor_sync(0xffffffffu, zlo, 2);
    zhi += __shfl_xor_sync(0xffffffffu, zhi, 1);
    zhi += __shfl_xor_sync(0xffffffffu, zhi, 2);

    size_t rb = (size_t)((b * KS8 + ks) * NN + row_lo);
    float* dlo = g_paccl + rb * EN + qid * 2;
    float* dhi = g_paccl + (rb + 8) * EN + qid * 2;
#pragma unroll
    for (int nt = 0; nt < 2; nt++) {
        *reinterpret_cast<float2*>(dlo + nt * 8) = make_float2(C[nt][0], C[nt][1]);
        *reinterpret_cast<float2*>(dhi + nt * 8) = make_float2(C[nt][2], C[nt][3]);
    }
    if (qid == 0) { g_pZl[rb] = zlo; g_pZl[rb + 8] = zhi; }
}

// ---------------- K4b: combine splits, divide, ELU, write output ----------------
__global__ void k4_comb(float* __restrict__ out) {
    int idx = blockIdx.x * 256 + threadIdx.x;    // over BB*NN*EN
    int c  = idx & (EN - 1);
    int ri = idx >> 4;
    int b  = ri >> 12;
    int i  = ri & (NN - 1);
    float a = 0.f, Z = 0.f;
#pragma unroll
    for (int sp = 0; sp < KS8; sp++) {
        size_t rb = ((size_t)(b * KS8 + sp) << 12) + i;
        a += g_paccl[rb * EN + c];
        Z += g_pZl[rb];
    }
    out[((size_t)b * NN + i) * EN + c] = eluf(a / Z);
}

// ---------------- launch ----------------
extern "C" void kernel_launch(void* const* d_in, const int* in_sizes, int n_in,
                              void* d_out, int out_size) {
    const float* fea = (const float*)d_in[0];   // [B,N,D]
    const float* adj = (const float*)d_in[1];   // [B,N,N]
    const float* Wh  = (const float*)d_in[2];   // [H,D,HID]
    const float* ah  = (const float*)d_in[3];   // [H,2*HID,1]
    const float* Wl  = (const float*)d_in[4];   // [H*HID,EN]
    const float* al  = (const float*)d_in[5];   // [2*EN,1]
    float* out = (float*)d_out;                 // [B,N,EN]

    (void)in_sizes; (void)n_in; (void)out_size;

    k0_pack<<<(BB * NN) / 8, 256>>>(adj);
    k1_wh  <<<(BB * HH * NN) / 8, 256>>>(fea, Wh, ah);
    k2t    <<<dim3(NN / 64, NSP2, BB * HH), 128>>>();
    k3f    <<<(BB * NN) / 8, 256>>>(Wl, al);
    k4t    <<<dim3(NN / 64, KS8, BB), 128>>>();
    k4_comb<<<(BB * NN * EN) / 256, 256>>>(out);
}